// round 12
// baseline (speedup 1.0000x reference)
#include <cuda_runtime.h>
#include <stdint.h>

// ---------------------------------------------------------------------------
// Problem constants (DSEC 480x640, 4x4 voxels, B=4)
// ---------------------------------------------------------------------------
#define NV0 120
#define NV1 160
#define NBATCH 4
#define KC (NBATCH * NV0 * NV1)   /* 76800 */
#define DIM 64

#define N_MAX (1 << 20)
#define E_MAX (1 << 23)
#define NB (1 << 20)              /* sort buckets */
#define NBLK (NB / 1024)
#define ENC_NEG_INF 0x007FFFFFu

// int32-wrapped sentinel: (int32)(76800*76800) = 1603272704
#define SENT32 1603272704
#define SENT64 5898240000ull
// biased (unsigned-order) sentinel: SENT32 ^ 0x80000000
#define USENT32 3750756352u

// Output layout (float32 flatten, reference return order):
#define OFF_POS   (KC * DIM)
#define OFF_BATCH (OFF_POS + KC * 3)
#define OFF_MASK  (OFF_BATCH + KC)
#define OFF_EI    (OFF_MASK + KC)

// ---------------------------------------------------------------------------
// Static device scratch
// ---------------------------------------------------------------------------
__device__ int            g_is64;
__device__ int            g_cluster[N_MAX];
__device__ unsigned int   g_counts[KC];
__device__ float          g_possum[KC * 3];
__device__ unsigned int   g_xmax[KC * DIM];
__device__ unsigned int   g_key32[E_MAX];     // monotone u32 key (i32 fast path)
__device__ unsigned short g_low[E_MAX];       // low key bits grouped by bucket
__device__ unsigned int   g_bcnt[NB];
__device__ unsigned int   g_incl[NB];
__device__ unsigned int   g_cursor[NB];       // running exclusive offsets
__device__ unsigned int   g_bsum[NBLK];

__device__ __forceinline__ unsigned int enc_f32(float v) {
    unsigned int u = __float_as_uint(v);
    return (u & 0x80000000u) ? ~u : (u | 0x80000000u);
}
__device__ __forceinline__ float dec_f32(unsigned int u) {
    u = (u & 0x80000000u) ? (u & 0x7FFFFFFFu) : ~u;
    return __uint_as_float(u);
}
__device__ __forceinline__ int ld_id(const void* p, long long i, int is64) {
    return is64 ? (int)((const long long*)p)[i] : ((const int*)p)[i];
}
__device__ __forceinline__ int clampi(int v, int lo, int hi) {
    return v < lo ? lo : (v > hi ? hi : v);
}

// monotone u64 key matching reference ascending order, ALL edges included
__device__ __forceinline__ unsigned long long edge_uk(int sc, int dc, int is64) {
    if (is64) {
        if (sc == dc) return SENT64;
        return (unsigned long long)(unsigned int)sc * 76800ull
             + (unsigned long long)(unsigned int)dc;
    }
    int key32 = (sc == dc) ? SENT32
              : (int)((unsigned int)sc * 76800u + (unsigned int)dc);  // wraps like ref
    return (unsigned long long)(((unsigned int)key32) ^ 0x80000000u); // signed order
}

// i32 key from clusters (biased unsigned order)
__device__ __forceinline__ unsigned int edge_k32(int sc, int dc) {
    int key32 = (sc == dc) ? SENT32
              : (int)((unsigned int)sc * 76800u + (unsigned int)dc);
    return ((unsigned int)key32) ^ 0x80000000u;
}

// i32 fast path: decode biased key via magic division (no 64-bit div).
// 76800 = 2^10 * 75;  floor(uk/76800) = umulhi(uk>>10, 57266231)  (exact)
// signed floor-div: 2^31 = 76800*27962 + 2048.
__device__ __forceinline__ void decode32(unsigned int uk,
                                         float* sf, float* df, bool* valid) {
    *valid = (uk < USENT32);
    unsigned int q = __umulhi(uk >> 10, 57266231u);
    unsigned int r = uk - q * 76800u;
    int qf; unsigned int rf;
    if (r >= 2048u) { qf = (int)q - 27962; rf = r - 2048u; }
    else            { qf = (int)q - 27963; rf = r + 74752u; }
    *sf = (float)qf;
    *df = (float)rf;
}

__device__ __forceinline__ void decode_key(unsigned long long uk, int is64,
                                           float* sf, float* df, bool* valid) {
    if (is64) {
        *valid = (uk < SENT64);
        *sf = (float)(long long)(uk / 76800ull);
        *df = (float)(long long)(uk % 76800ull);
    } else {
        decode32((unsigned int)uk, sf, df, valid);
    }
}

// emit one sorted run element (shared by all emit paths)
__device__ __forceinline__ void emit_pos(float* __restrict__ out, int E,
                                         long long out_size, unsigned int bucket,
                                         int sh, int is64, unsigned int v,
                                         bool first, long long p) {
    const long long off_ei = OFF_EI;
    const long long off_em = off_ei + 2ll * E;
    unsigned long long uk = (((unsigned long long)bucket) << sh) | v;
    float sf, df; bool valid;
    decode_key(uk, is64, &sf, &df, &valid);
    bool mask = first && valid;
    if (off_ei + p < out_size)     out[off_ei + p]     = mask ? sf   : -1.0f;
    if (off_ei + E + p < out_size) out[off_ei + E + p] = mask ? df   : -1.0f;
    if (off_em + p < out_size)     out[off_em + p]     = mask ? 1.0f : 0.0f;
}

// ---------------------------------------------------------------------------
// init (+ dtype sniff): vectorized uint4 stores
// ---------------------------------------------------------------------------
__global__ void init_kernel(const unsigned int* ew) {
    int i = blockIdx.x * blockDim.x + threadIdx.x;
    if (i == 0) {
        unsigned int o = 0;
        for (int k = 1; k < 128; k += 2) o |= ew[k];
        g_is64 = (o == 0u) ? 1 : 0;
    }
    if (i >= KC * DIM / 4) return;
    ((uint4*)g_xmax)[i] = make_uint4(ENC_NEG_INF, ENC_NEG_INF, ENC_NEG_INF, ENC_NEG_INF);
    if (i < KC / 4)     ((uint4*)g_counts)[i] = make_uint4(0u, 0u, 0u, 0u);
    if (i < KC * 3 / 4) ((uint4*)g_possum)[i] = make_uint4(0u, 0u, 0u, 0u);
    if (i < NB / 4)     ((uint4*)g_bcnt)[i]   = make_uint4(0u, 0u, 0u, 0u);
}

// ---------------------------------------------------------------------------
// cluster: one thread per node (must precede the stream fork)
// ---------------------------------------------------------------------------
__global__ void cluster_kernel(const float* __restrict__ pos,
                               const void* batch, int N) {
    int i = blockIdx.x * blockDim.x + threadIdx.x;
    if (i >= N) return;
    int is64 = g_is64;
    float p0 = pos[3 * i + 0];
    float p1 = pos[3 * i + 1];
    float p2 = pos[3 * i + 2];
    int c0 = clampi((int)floorf(p1 * 0.25f), 0, NV0 - 1);
    int c1 = clampi((int)floorf(p2 * 0.25f), 0, NV1 - 1);
    int b  = clampi(ld_id(batch, i, is64), 0, NBATCH - 1);
    int c  = c0 + c1 * NV0 + b * (NV0 * NV1);
    g_cluster[i] = c;
    atomicAdd(&g_counts[c], 1u);
    atomicAdd(&g_possum[3 * c + 0], p0);
    atomicAdd(&g_possum[3 * c + 1], p1);
    atomicAdd(&g_possum[3 * c + 2], p2);
}

// x scatter-max: one warp per node, float2 load, shfl redistribution so the
// two atomic instructions hit CONTIGUOUS 128B ranges (4 sectors each = 8
// sectors/node, the minimum; the 2*lane layout cost 16 sectors/node).
__global__ void xmax_kernel(const float* __restrict__ x, int N) {
    int gw   = (blockIdx.x * blockDim.x + threadIdx.x) >> 5;
    int lane = threadIdx.x & 31;
    if (gw >= N) return;
    int c = g_cluster[gw];
    float2 v = ((const float2*)(x + (size_t)gw * DIM))[lane];
    unsigned int e0 = enc_f32(v.x);   // x[2*lane]
    unsigned int e1 = enc_f32(v.y);   // x[2*lane+1]
    // lane wants enc(x[lane]) and enc(x[lane+32])
    unsigned int s0a = __shfl_sync(0xFFFFFFFFu, e0, lane >> 1);
    unsigned int s1a = __shfl_sync(0xFFFFFFFFu, e1, lane >> 1);
    unsigned int lo  = (lane & 1) ? s1a : s0a;
    unsigned int s0b = __shfl_sync(0xFFFFFFFFu, e0, (lane >> 1) + 16);
    unsigned int s1b = __shfl_sync(0xFFFFFFFFu, e1, (lane >> 1) + 16);
    unsigned int hi  = (lane & 1) ? s1b : s0b;
    unsigned int* dst = g_xmax + (size_t)c * DIM;
    atomicMax(&dst[lane],      lo);
    atomicMax(&dst[lane + 32], hi);
}

// ---------------------------------------------------------------------------
// edgekey: 4 edges per thread (i32 fast path), store keys + histogram
// ---------------------------------------------------------------------------
__global__ void edgekey_kernel(const void* eidx, int N, int E) {
    int t = blockIdx.x * blockDim.x + threadIdx.x;
    int is64 = g_is64;
    if (!is64) {
        if ((E & 3) == 0) {
            int nq = E >> 2;
            if (t >= nq) return;
            int4 uu = ((const int4*)eidx)[t];
            int4 vv = ((const int4*)((const int*)eidx + E))[t];
            int sc0 = g_cluster[clampi(uu.x, 0, N - 1)];
            int sc1 = g_cluster[clampi(uu.y, 0, N - 1)];
            int sc2 = g_cluster[clampi(uu.z, 0, N - 1)];
            int sc3 = g_cluster[clampi(uu.w, 0, N - 1)];
            int dc0 = g_cluster[clampi(vv.x, 0, N - 1)];
            int dc1 = g_cluster[clampi(vv.y, 0, N - 1)];
            int dc2 = g_cluster[clampi(vv.z, 0, N - 1)];
            int dc3 = g_cluster[clampi(vv.w, 0, N - 1)];
            unsigned int k0 = edge_k32(sc0, dc0);
            unsigned int k1 = edge_k32(sc1, dc1);
            unsigned int k2 = edge_k32(sc2, dc2);
            unsigned int k3 = edge_k32(sc3, dc3);
            ((uint4*)g_key32)[t] = make_uint4(k0, k1, k2, k3);
            atomicAdd(&g_bcnt[k0 >> 12], 1u);
            atomicAdd(&g_bcnt[k1 >> 12], 1u);
            atomicAdd(&g_bcnt[k2 >> 12], 1u);
            atomicAdd(&g_bcnt[k3 >> 12], 1u);
        } else {
            if (t >= E) return;
            int u = clampi(((const int*)eidx)[t], 0, N - 1);
            int v = clampi(((const int*)eidx)[(size_t)E + t], 0, N - 1);
            unsigned int k = edge_k32(g_cluster[u], g_cluster[v]);
            g_key32[t] = k;
            atomicAdd(&g_bcnt[k >> 12], 1u);
        }
    } else {
        if (t >= E) return;
        int u = clampi(ld_id(eidx, t, 1), 0, N - 1);
        int v = clampi(ld_id(eidx, (long long)E + t, 1), 0, N - 1);
        unsigned long long uk = edge_uk(g_cluster[u], g_cluster[v], 1);
        unsigned int b = (unsigned int)(uk >> 13);
        if (b < NB) atomicAdd(&g_bcnt[b], 1u);
    }
}

// -- shfl-based scans ------------------------------------------------------
__device__ __forceinline__ unsigned int blk_incl_scan_1024(unsigned int v,
                                                           unsigned int* wsum) {
    int t = threadIdx.x;
    #pragma unroll
    for (int d = 1; d < 32; d <<= 1) {
        unsigned int u = __shfl_up_sync(0xFFFFFFFFu, v, d);
        if ((t & 31) >= d) v += u;
    }
    if ((t & 31) == 31) wsum[t >> 5] = v;
    __syncthreads();
    if (t < 32) {
        unsigned int s = wsum[t];
        #pragma unroll
        for (int d = 1; d < 32; d <<= 1) {
            unsigned int u = __shfl_up_sync(0xFFFFFFFFu, s, d);
            if (t >= d) s += u;
        }
        wsum[t] = s;
    }
    __syncthreads();
    if (t >= 32) v += wsum[(t >> 5) - 1];
    return v;
}

__global__ void scan1_kernel() {
    __shared__ unsigned int wsum[32];
    int base = blockIdx.x * 1024;
    unsigned int v = blk_incl_scan_1024(g_bcnt[base + threadIdx.x], wsum);
    g_incl[base + threadIdx.x] = v;
    if (threadIdx.x == 1023) g_bsum[blockIdx.x] = v;
}
__global__ void scan2_kernel() {
    __shared__ unsigned int wsum[32];
    unsigned int orig = g_bsum[threadIdx.x];
    unsigned int v = blk_incl_scan_1024(orig, wsum);
    g_bsum[threadIdx.x] = v - orig;   // exclusive
}
__global__ void scan3_kernel() {      // finalize incl + preload cursors
    int i = blockIdx.x * blockDim.x + threadIdx.x;
    if (i >= NB) return;
    unsigned int incl = g_incl[i] + g_bsum[i >> 10];
    g_incl[i]   = incl;
    g_cursor[i] = incl - g_bcnt[i];   // exclusive start
}

// ---------------------------------------------------------------------------
// scatter: 8 edges per thread (2x uint4), 8 independent atomic chains
// ---------------------------------------------------------------------------
__global__ void scatter_kernel(const void* eidx, int N, int E) {
    int t = blockIdx.x * blockDim.x + threadIdx.x;
    int is64 = g_is64;
    if (!is64) {
        int noct = E >> 3;
        if (t < noct) {
            uint4 a = ((const uint4*)g_key32)[2 * t];
            uint4 b = ((const uint4*)g_key32)[2 * t + 1];
            unsigned int p0 = atomicAdd(&g_cursor[a.x >> 12], 1u);
            unsigned int p1 = atomicAdd(&g_cursor[a.y >> 12], 1u);
            unsigned int p2 = atomicAdd(&g_cursor[a.z >> 12], 1u);
            unsigned int p3 = atomicAdd(&g_cursor[a.w >> 12], 1u);
            unsigned int p4 = atomicAdd(&g_cursor[b.x >> 12], 1u);
            unsigned int p5 = atomicAdd(&g_cursor[b.y >> 12], 1u);
            unsigned int p6 = atomicAdd(&g_cursor[b.z >> 12], 1u);
            unsigned int p7 = atomicAdd(&g_cursor[b.w >> 12], 1u);
            if (p0 < (unsigned int)E) g_low[p0] = (unsigned short)(a.x & 0xFFFu);
            if (p1 < (unsigned int)E) g_low[p1] = (unsigned short)(a.y & 0xFFFu);
            if (p2 < (unsigned int)E) g_low[p2] = (unsigned short)(a.z & 0xFFFu);
            if (p3 < (unsigned int)E) g_low[p3] = (unsigned short)(a.w & 0xFFFu);
            if (p4 < (unsigned int)E) g_low[p4] = (unsigned short)(b.x & 0xFFFu);
            if (p5 < (unsigned int)E) g_low[p5] = (unsigned short)(b.y & 0xFFFu);
            if (p6 < (unsigned int)E) g_low[p6] = (unsigned short)(b.z & 0xFFFu);
            if (p7 < (unsigned int)E) g_low[p7] = (unsigned short)(b.w & 0xFFFu);
        }
        if (t == 0) {
            for (int e = E & ~7; e < E; e++) {
                unsigned int k = g_key32[e];
                unsigned int p = atomicAdd(&g_cursor[k >> 12], 1u);
                if (p < (unsigned int)E) g_low[p] = (unsigned short)(k & 0xFFFu);
            }
        }
    } else {
        if (t >= E) return;
        int u = clampi(ld_id(eidx, t, 1), 0, N - 1);
        int v = clampi(ld_id(eidx, (long long)E + t, 1), 0, N - 1);
        unsigned long long uk = edge_uk(g_cluster[u], g_cluster[v], 1);
        unsigned int b   = (unsigned int)(uk >> 13);
        unsigned int low = (unsigned int)(uk & 0x1FFFu);
        if (b >= NB) return;
        unsigned int pos = atomicAdd(&g_cursor[b], 1u);
        if (pos < (unsigned int)E) g_low[pos] = (unsigned short)low;
    }
}

// full-warp path for one bucket (n <= 32: 32-wide bitonic; else odd-even)
__device__ void emit_bucket_fullwarp(float* __restrict__ out, int E,
                                     long long out_size, unsigned int bucket,
                                     unsigned int start, unsigned int n,
                                     int sh, int is64, int lane) {
    if (n <= 32) {
        unsigned int v = (lane < (int)n) ? (unsigned int)g_low[start + lane]
                                         : 0xFFFFFFFFu;
        #pragma unroll
        for (unsigned int k = 2; k <= 32; k <<= 1) {
            for (unsigned int j = k >> 1; j > 0; j >>= 1) {
                unsigned int o = __shfl_xor_sync(0xFFFFFFFFu, v, j);
                bool dirUp = ((lane & k) == 0);
                bool lower = ((lane & j) == 0);
                unsigned int mn = v < o ? v : o, mx = v < o ? o : v;
                v = (lower == dirUp) ? mn : mx;
            }
        }
        unsigned int prev = __shfl_up_sync(0xFFFFFFFFu, v, 1);
        if (lane < (int)n) {
            bool first = (lane == 0) || (v != prev);
            emit_pos(out, E, out_size, bucket, sh, is64, v, first,
                     (long long)(start + lane));
        }
    } else {
        unsigned short* a = g_low + start;
        unsigned int eq = 1;
        unsigned short v0 = a[0];
        for (unsigned int i = lane; i < n; i += 32)
            if (a[i] != v0) eq = 0;
        eq = __all_sync(0xFFFFFFFFu, eq);
        if (!eq) {
            for (unsigned int pass = 0; pass < n; ++pass) {
                unsigned int st = pass & 1u;
                for (unsigned int i = st + 2u * lane; i + 1 < n; i += 64u) {
                    unsigned short x0 = a[i], x1 = a[i + 1];
                    if (x0 > x1) { a[i] = x1; a[i + 1] = x0; }
                }
                __syncwarp();
            }
        }
        for (unsigned int i = lane; i < n; i += 32) {
            unsigned int v = a[i];
            bool first = (i == 0) || (v != (unsigned int)a[i - 1]);
            emit_pos(out, E, out_size, bucket, sh, is64, v, first,
                     (long long)(start + i));
        }
    }
}

// TWO buckets per warp: 16-lane sub-warp bitonic for n<=16 (99.6% of buckets)
__global__ void bucket_emit_kernel(float* __restrict__ out, int E, long long out_size) {
    int gw   = (blockIdx.x * blockDim.x + threadIdx.x) >> 5;
    int lane = threadIdx.x & 31;
    unsigned int b0 = (unsigned int)gw * 2u;
    if (b0 >= NB) return;
    unsigned int start0 = (b0 == 0u) ? 0u : g_incl[b0 - 1];
    unsigned int end0   = g_incl[b0];
    unsigned int end1   = g_incl[b0 + 1];
    unsigned int n0 = end0 - start0, n1 = end1 - end0;
    if ((n0 | n1) == 0u) return;
    int is64 = g_is64;
    int sh = is64 ? 13 : 12;

    if (n0 <= 16u && n1 <= 16u) {
        int half = lane >> 4, l = lane & 15;
        unsigned int start  = half ? end0 : start0;
        unsigned int n      = half ? n1 : n0;
        unsigned int bucket = b0 + (unsigned int)half;
        unsigned int v = ((unsigned int)l < n) ? (unsigned int)g_low[start + l]
                                               : 0xFFFFFFFFu;
        #pragma unroll
        for (unsigned int k = 2; k <= 16; k <<= 1) {
            for (unsigned int j = k >> 1; j > 0; j >>= 1) {
                unsigned int o = __shfl_xor_sync(0xFFFFFFFFu, v, j);
                bool dirUp = (((unsigned int)l & k) == 0);
                bool lower = (((unsigned int)l & j) == 0);
                unsigned int mn = v < o ? v : o, mx = v < o ? o : v;
                v = (lower == dirUp) ? mn : mx;
            }
        }
        unsigned int prev = __shfl_up_sync(0xFFFFFFFFu, v, 1);
        if ((unsigned int)l < n) {
            bool first = (l == 0) || (v != prev);
            emit_pos(out, E, out_size, bucket, sh, is64, v, first,
                     (long long)(start + (unsigned int)l));
        }
    } else {
        if (n0) emit_bucket_fullwarp(out, E, out_size, b0,     start0, n0, sh, is64, lane);
        if (n1) emit_bucket_fullwarp(out, E, out_size, b0 + 1, end0,   n1, sh, is64, lane);
    }
}

__global__ void finalize_kernel(float* __restrict__ out, long long out_size) {
    int i = blockIdx.x * blockDim.x + threadIdx.x;
    if (i >= KC * DIM) return;
    {
        int c = i / DIM;
        float v = (g_counts[c] > 0u) ? dec_f32(g_xmax[i]) : 0.0f;
        if (i < out_size) out[i] = v;
    }
    if (i < KC * 3) {
        int c = i / 3;
        unsigned int cnt = g_counts[c];
        if (OFF_POS + i < out_size)
            out[OFF_POS + i] = g_possum[i] / (float)(cnt > 0u ? cnt : 1u);
    }
    if (i < KC) {
        if (OFF_BATCH + i < out_size) out[OFF_BATCH + i] = (float)(i / (NV0 * NV1));
        if (OFF_MASK + i < out_size)  out[OFF_MASK + i]  = (g_counts[i] > 0u) ? 1.0f : 0.0f;
    }
}

// ---------------------------------------------------------------------------
// Launch: fork-join streams — edge chain || xmax chain
// ---------------------------------------------------------------------------
extern "C" void kernel_launch(void* const* d_in, const int* in_sizes, int n_in,
                              void* d_out, int out_size) {
    int ib = 0;
    for (int i = 1; i < n_in && i < 4; i++)
        if (in_sizes[i] < in_sizes[ib]) ib = i;
    long long N = in_sizes[ib];
    int ix = -1, ip = -1, ie = -1;
    for (int i = 0; i < n_in && i < 4; i++) {
        if (i == ib) continue;
        long long s = in_sizes[i];
        if (s == 64 * N)     ix = i;
        else if (s == 3 * N) ip = i;
        else                 ie = i;
    }
    if (ix < 0 || ip < 0 || ie < 0) { ix = 0; ip = 1; ib = 2; ie = 3; }

    const float* x    = (const float*)d_in[ix];
    const float* pos  = (const float*)d_in[ip];
    const void*  bat  = d_in[ib];
    const void*  eidx = d_in[ie];
    float*       out  = (float*)d_out;

    int Ni = (int)N;
    int E  = in_sizes[ie] / 2;
    if (Ni > N_MAX) Ni = N_MAX;
    if (E > E_MAX)  E  = E_MAX;

    static cudaStream_t s1 = nullptr;
    static cudaEvent_t evFork = nullptr, evJoin = nullptr;
    if (!s1) {
        cudaStreamCreateWithFlags(&s1, cudaStreamNonBlocking);
        cudaEventCreateWithFlags(&evFork, cudaEventDisableTiming);
        cudaEventCreateWithFlags(&evJoin, cudaEventDisableTiming);
    }

    const int T = 256;
    init_kernel<<<(KC * DIM / 4 + T - 1) / T, T>>>((const unsigned int*)eidx);
    cluster_kernel<<<(Ni + T - 1) / T, T>>>(pos, bat, Ni);

    // fork: side stream runs the x-max chain
    cudaEventRecord(evFork, 0);
    cudaStreamWaitEvent(s1, evFork, 0);
    xmax_kernel<<<(int)(((size_t)Ni * 32 + T - 1) / T), T, 0, s1>>>(x, Ni);
    finalize_kernel<<<(KC * DIM + T - 1) / T, T, 0, s1>>>(out, (long long)out_size);
    cudaEventRecord(evJoin, s1);

    // main stream: the edge chain
    edgekey_kernel<<<(E + T - 1) / T, T>>>(eidx, Ni, E);
    scan1_kernel<<<NBLK, 1024>>>();
    scan2_kernel<<<1, 1024>>>();
    scan3_kernel<<<NB / 1024, 1024>>>();
    scatter_kernel<<<(E + T - 1) / T, T>>>(eidx, Ni, E);
    bucket_emit_kernel<<<NB / 16, T>>>(out, E, (long long)out_size);

    // join
    cudaStreamWaitEvent(0, evJoin, 0);
}

// round 13
// speedup vs baseline: 1.0333x; 1.0333x over previous
#include <cuda_runtime.h>
#include <stdint.h>

// ---------------------------------------------------------------------------
// Problem constants (DSEC 480x640, 4x4 voxels, B=4)
// ---------------------------------------------------------------------------
#define NV0 120
#define NV1 160
#define NBATCH 4
#define KC (NBATCH * NV0 * NV1)   /* 76800 */
#define DIM 64

#define N_MAX (1 << 20)
#define E_MAX (1 << 23)
#define NB (1 << 20)              /* sort buckets */
#define NBLK (NB / 1024)
#define ENC_NEG_INF 0x007FFFFFu

// int32-wrapped sentinel: (int32)(76800*76800) = 1603272704
#define SENT32 1603272704
#define SENT64 5898240000ull
// biased (unsigned-order) sentinel: SENT32 ^ 0x80000000
#define USENT32 3750756352u

// Output layout (float32 flatten, reference return order):
#define OFF_POS   (KC * DIM)
#define OFF_BATCH (OFF_POS + KC * 3)
#define OFF_MASK  (OFF_BATCH + KC)
#define OFF_EI    (OFF_MASK + KC)

// ---------------------------------------------------------------------------
// Static device scratch
// ---------------------------------------------------------------------------
__device__ int            g_is64;
__device__ int            g_cluster[N_MAX];
__device__ unsigned int   g_counts[KC];
__device__ float          g_possum[KC * 3];
__device__ unsigned int   g_xmax[KC * DIM];
__device__ unsigned int   g_key32[E_MAX];     // monotone u32 key (i32 fast path)
__device__ unsigned short g_low[E_MAX];       // low key bits grouped by bucket
__device__ unsigned int   g_bcnt[NB];         // hist -> (scan3) inclusive cursor
__device__ unsigned int   g_incl[NB];         // inclusive scan (stable, for emit)
__device__ unsigned int   g_bsum[NBLK];

__device__ __forceinline__ unsigned int enc_f32(float v) {
    unsigned int u = __float_as_uint(v);
    return (u & 0x80000000u) ? ~u : (u | 0x80000000u);
}
__device__ __forceinline__ float dec_f32(unsigned int u) {
    u = (u & 0x80000000u) ? (u & 0x7FFFFFFFu) : ~u;
    return __uint_as_float(u);
}
__device__ __forceinline__ int ld_id(const void* p, long long i, int is64) {
    return is64 ? (int)((const long long*)p)[i] : ((const int*)p)[i];
}
__device__ __forceinline__ int clampi(int v, int lo, int hi) {
    return v < lo ? lo : (v > hi ? hi : v);
}

// monotone u64 key matching reference ascending order, ALL edges included
__device__ __forceinline__ unsigned long long edge_uk(int sc, int dc, int is64) {
    if (is64) {
        if (sc == dc) return SENT64;
        return (unsigned long long)(unsigned int)sc * 76800ull
             + (unsigned long long)(unsigned int)dc;
    }
    int key32 = (sc == dc) ? SENT32
              : (int)((unsigned int)sc * 76800u + (unsigned int)dc);  // wraps like ref
    return (unsigned long long)(((unsigned int)key32) ^ 0x80000000u); // signed order
}

// i32 key from clusters (biased unsigned order)
__device__ __forceinline__ unsigned int edge_k32(int sc, int dc) {
    int key32 = (sc == dc) ? SENT32
              : (int)((unsigned int)sc * 76800u + (unsigned int)dc);
    return ((unsigned int)key32) ^ 0x80000000u;
}

// i32 fast path: decode biased key via magic division (no 64-bit div).
// 76800 = 2^10 * 75;  floor(uk/76800) = umulhi(uk>>10, 57266231)  (exact)
// signed floor-div: 2^31 = 76800*27962 + 2048.
__device__ __forceinline__ void decode32(unsigned int uk,
                                         float* sf, float* df, bool* valid) {
    *valid = (uk < USENT32);
    unsigned int q = __umulhi(uk >> 10, 57266231u);
    unsigned int r = uk - q * 76800u;
    int qf; unsigned int rf;
    if (r >= 2048u) { qf = (int)q - 27962; rf = r - 2048u; }
    else            { qf = (int)q - 27963; rf = r + 74752u; }
    *sf = (float)qf;
    *df = (float)rf;
}

__device__ __forceinline__ void decode_key(unsigned long long uk, int is64,
                                           float* sf, float* df, bool* valid) {
    if (is64) {
        *valid = (uk < SENT64);
        *sf = (float)(long long)(uk / 76800ull);
        *df = (float)(long long)(uk % 76800ull);
    } else {
        decode32((unsigned int)uk, sf, df, valid);
    }
}

// emit one sorted run element (no bounds checks: layout exact by construction)
__device__ __forceinline__ void emit_pos(float* __restrict__ out, int E,
                                         unsigned int bucket,
                                         int sh, int is64, unsigned int v,
                                         bool first, long long p) {
    const long long off_ei = OFF_EI;
    const long long off_em = off_ei + 2ll * E;
    unsigned long long uk = (((unsigned long long)bucket) << sh) | v;
    float sf, df; bool valid;
    decode_key(uk, is64, &sf, &df, &valid);
    bool mask = first && valid;
    out[off_ei + p]     = mask ? sf   : -1.0f;
    out[off_ei + E + p] = mask ? df   : -1.0f;
    out[off_em + p]     = mask ? 1.0f : 0.0f;
}

// ---------------------------------------------------------------------------
// init (+ dtype sniff): vectorized uint4 stores
// ---------------------------------------------------------------------------
__global__ void init_kernel(const unsigned int* ew) {
    int i = blockIdx.x * blockDim.x + threadIdx.x;
    if (i == 0) {
        unsigned int o = 0;
        for (int k = 1; k < 128; k += 2) o |= ew[k];
        g_is64 = (o == 0u) ? 1 : 0;
    }
    if (i >= KC * DIM / 4) return;
    ((uint4*)g_xmax)[i] = make_uint4(ENC_NEG_INF, ENC_NEG_INF, ENC_NEG_INF, ENC_NEG_INF);
    if (i < KC / 4)     ((uint4*)g_counts)[i] = make_uint4(0u, 0u, 0u, 0u);
    if (i < KC * 3 / 4) ((uint4*)g_possum)[i] = make_uint4(0u, 0u, 0u, 0u);
    if (i < NB / 4)     ((uint4*)g_bcnt)[i]   = make_uint4(0u, 0u, 0u, 0u);
}

// ---------------------------------------------------------------------------
// cluster: one thread per node
// ---------------------------------------------------------------------------
__global__ void cluster_kernel(const float* __restrict__ pos,
                               const void* batch, int N) {
    int i = blockIdx.x * blockDim.x + threadIdx.x;
    if (i >= N) return;
    int is64 = g_is64;
    float p0 = pos[3 * i + 0];
    float p1 = pos[3 * i + 1];
    float p2 = pos[3 * i + 2];
    int c0 = clampi((int)floorf(p1 * 0.25f), 0, NV0 - 1);
    int c1 = clampi((int)floorf(p2 * 0.25f), 0, NV1 - 1);
    int b  = clampi(ld_id(batch, i, is64), 0, NBATCH - 1);
    int c  = c0 + c1 * NV0 + b * (NV0 * NV1);
    g_cluster[i] = c;
    atomicAdd(&g_counts[c], 1u);
    atomicAdd(&g_possum[3 * c + 0], p0);
    atomicAdd(&g_possum[3 * c + 1], p1);
    atomicAdd(&g_possum[3 * c + 2], p2);
}

// x scatter-max: round-7 proven form — one warp per node, float2 loads,
// 2 spread atomics per lane (measured 51.8us; all deviations regressed)
__global__ void xmax_kernel(const float* __restrict__ x, int N) {
    int gw   = (blockIdx.x * blockDim.x + threadIdx.x) >> 5;
    int lane = threadIdx.x & 31;
    if (gw >= N) return;
    int c = g_cluster[gw];
    float2 v = ((const float2*)(x + (size_t)gw * DIM))[lane];
    unsigned int* dst = g_xmax + (size_t)c * DIM;
    atomicMax(&dst[2 * lane],     enc_f32(v.x));
    atomicMax(&dst[2 * lane + 1], enc_f32(v.y));
}

// ---------------------------------------------------------------------------
// edgekey: 4 edges per thread (i32 fast path), store keys + histogram
// ---------------------------------------------------------------------------
__global__ void edgekey_kernel(const void* eidx, int N, int E) {
    int t = blockIdx.x * blockDim.x + threadIdx.x;
    int is64 = g_is64;
    if (!is64) {
        if ((E & 3) == 0) {
            int nq = E >> 2;
            if (t >= nq) return;
            int4 uu = ((const int4*)eidx)[t];
            int4 vv = ((const int4*)((const int*)eidx + E))[t];
            int sc0 = g_cluster[clampi(uu.x, 0, N - 1)];
            int sc1 = g_cluster[clampi(uu.y, 0, N - 1)];
            int sc2 = g_cluster[clampi(uu.z, 0, N - 1)];
            int sc3 = g_cluster[clampi(uu.w, 0, N - 1)];
            int dc0 = g_cluster[clampi(vv.x, 0, N - 1)];
            int dc1 = g_cluster[clampi(vv.y, 0, N - 1)];
            int dc2 = g_cluster[clampi(vv.z, 0, N - 1)];
            int dc3 = g_cluster[clampi(vv.w, 0, N - 1)];
            unsigned int k0 = edge_k32(sc0, dc0);
            unsigned int k1 = edge_k32(sc1, dc1);
            unsigned int k2 = edge_k32(sc2, dc2);
            unsigned int k3 = edge_k32(sc3, dc3);
            ((uint4*)g_key32)[t] = make_uint4(k0, k1, k2, k3);
            atomicAdd(&g_bcnt[k0 >> 12], 1u);
            atomicAdd(&g_bcnt[k1 >> 12], 1u);
            atomicAdd(&g_bcnt[k2 >> 12], 1u);
            atomicAdd(&g_bcnt[k3 >> 12], 1u);
        } else {
            if (t >= E) return;
            int u = clampi(((const int*)eidx)[t], 0, N - 1);
            int v = clampi(((const int*)eidx)[(size_t)E + t], 0, N - 1);
            unsigned int k = edge_k32(g_cluster[u], g_cluster[v]);
            g_key32[t] = k;
            atomicAdd(&g_bcnt[k >> 12], 1u);
        }
    } else {
        if (t >= E) return;
        int u = clampi(ld_id(eidx, t, 1), 0, N - 1);
        int v = clampi(ld_id(eidx, (long long)E + t, 1), 0, N - 1);
        unsigned long long uk = edge_uk(g_cluster[u], g_cluster[v], 1);
        atomicAdd(&g_bcnt[(unsigned int)(uk >> 13)], 1u);
    }
}

// -- shfl-based scans ------------------------------------------------------
__device__ __forceinline__ unsigned int blk_incl_scan_1024(unsigned int v,
                                                           unsigned int* wsum) {
    int t = threadIdx.x;
    #pragma unroll
    for (int d = 1; d < 32; d <<= 1) {
        unsigned int u = __shfl_up_sync(0xFFFFFFFFu, v, d);
        if ((t & 31) >= d) v += u;
    }
    if ((t & 31) == 31) wsum[t >> 5] = v;
    __syncthreads();
    if (t < 32) {
        unsigned int s = wsum[t];
        #pragma unroll
        for (int d = 1; d < 32; d <<= 1) {
            unsigned int u = __shfl_up_sync(0xFFFFFFFFu, s, d);
            if (t >= d) s += u;
        }
        wsum[t] = s;
    }
    __syncthreads();
    if (t >= 32) v += wsum[(t >> 5) - 1];
    return v;
}

__global__ void scan1_kernel() {
    __shared__ unsigned int wsum[32];
    int base = blockIdx.x * 1024;
    unsigned int v = blk_incl_scan_1024(g_bcnt[base + threadIdx.x], wsum);
    g_incl[base + threadIdx.x] = v;
    if (threadIdx.x == 1023) g_bsum[blockIdx.x] = v;
}
__global__ void scan2_kernel() {
    __shared__ unsigned int wsum[32];
    unsigned int orig = g_bsum[threadIdx.x];
    unsigned int v = blk_incl_scan_1024(orig, wsum);
    g_bsum[threadIdx.x] = v - orig;   // exclusive
}
__global__ void scan3_kernel() {
    // finalize incl; ALSO store inclusive offset into bcnt (reused as a
    // top-down cursor by scatter: pos = atomicSub(bcnt[b],1) - 1)
    int i = blockIdx.x * blockDim.x + threadIdx.x;
    if (i >= NB) return;
    unsigned int incl = g_incl[i] + g_bsum[i >> 10];
    g_incl[i] = incl;
    g_bcnt[i] = incl;
}

// ---------------------------------------------------------------------------
// scatter: 8 edges per thread; bucket filled top-down via atomicSub on bcnt
// ---------------------------------------------------------------------------
__global__ void scatter_kernel(const void* eidx, int N, int E) {
    int t = blockIdx.x * blockDim.x + threadIdx.x;
    int is64 = g_is64;
    if (!is64) {
        int noct = E >> 3;
        if (t < noct) {
            uint4 a = ((const uint4*)g_key32)[2 * t];
            uint4 b = ((const uint4*)g_key32)[2 * t + 1];
            unsigned int p0 = atomicSub(&g_bcnt[a.x >> 12], 1u) - 1u;
            unsigned int p1 = atomicSub(&g_bcnt[a.y >> 12], 1u) - 1u;
            unsigned int p2 = atomicSub(&g_bcnt[a.z >> 12], 1u) - 1u;
            unsigned int p3 = atomicSub(&g_bcnt[a.w >> 12], 1u) - 1u;
            unsigned int p4 = atomicSub(&g_bcnt[b.x >> 12], 1u) - 1u;
            unsigned int p5 = atomicSub(&g_bcnt[b.y >> 12], 1u) - 1u;
            unsigned int p6 = atomicSub(&g_bcnt[b.z >> 12], 1u) - 1u;
            unsigned int p7 = atomicSub(&g_bcnt[b.w >> 12], 1u) - 1u;
            g_low[p0] = (unsigned short)(a.x & 0xFFFu);
            g_low[p1] = (unsigned short)(a.y & 0xFFFu);
            g_low[p2] = (unsigned short)(a.z & 0xFFFu);
            g_low[p3] = (unsigned short)(a.w & 0xFFFu);
            g_low[p4] = (unsigned short)(b.x & 0xFFFu);
            g_low[p5] = (unsigned short)(b.y & 0xFFFu);
            g_low[p6] = (unsigned short)(b.z & 0xFFFu);
            g_low[p7] = (unsigned short)(b.w & 0xFFFu);
        }
        if (t == 0) {
            for (int e = E & ~7; e < E; e++) {
                unsigned int k = g_key32[e];
                unsigned int p = atomicSub(&g_bcnt[k >> 12], 1u) - 1u;
                g_low[p] = (unsigned short)(k & 0xFFFu);
            }
        }
    } else {
        if (t >= E) return;
        int u = clampi(ld_id(eidx, t, 1), 0, N - 1);
        int v = clampi(ld_id(eidx, (long long)E + t, 1), 0, N - 1);
        unsigned long long uk = edge_uk(g_cluster[u], g_cluster[v], 1);
        unsigned int b   = (unsigned int)(uk >> 13);
        unsigned int pos = atomicSub(&g_bcnt[b], 1u) - 1u;
        g_low[pos] = (unsigned short)(uk & 0x1FFFu);
    }
}

// full-warp path for one bucket (n <= 32: 32-wide bitonic; else odd-even)
__device__ void emit_bucket_fullwarp(float* __restrict__ out, int E,
                                     unsigned int bucket,
                                     unsigned int start, unsigned int n,
                                     int sh, int is64, int lane) {
    if (n <= 32) {
        unsigned int v = (lane < (int)n) ? (unsigned int)g_low[start + lane]
                                         : 0xFFFFFFFFu;
        #pragma unroll
        for (unsigned int k = 2; k <= 32; k <<= 1) {
            for (unsigned int j = k >> 1; j > 0; j >>= 1) {
                unsigned int o = __shfl_xor_sync(0xFFFFFFFFu, v, j);
                bool dirUp = ((lane & k) == 0);
                bool lower = ((lane & j) == 0);
                unsigned int mn = v < o ? v : o, mx = v < o ? o : v;
                v = (lower == dirUp) ? mn : mx;
            }
        }
        unsigned int prev = __shfl_up_sync(0xFFFFFFFFu, v, 1);
        if (lane < (int)n) {
            bool first = (lane == 0) || (v != prev);
            emit_pos(out, E, bucket, sh, is64, v, first, (long long)(start + lane));
        }
    } else {
        unsigned short* a = g_low + start;
        unsigned int eq = 1;
        unsigned short v0 = a[0];
        for (unsigned int i = lane; i < n; i += 32)
            if (a[i] != v0) eq = 0;
        eq = __all_sync(0xFFFFFFFFu, eq);
        if (!eq) {
            for (unsigned int pass = 0; pass < n; ++pass) {
                unsigned int st = pass & 1u;
                for (unsigned int i = st + 2u * lane; i + 1 < n; i += 64u) {
                    unsigned short x0 = a[i], x1 = a[i + 1];
                    if (x0 > x1) { a[i] = x1; a[i + 1] = x0; }
                }
                __syncwarp();
            }
        }
        for (unsigned int i = lane; i < n; i += 32) {
            unsigned int v = a[i];
            bool first = (i == 0) || (v != (unsigned int)a[i - 1]);
            emit_pos(out, E, bucket, sh, is64, v, first, (long long)(start + i));
        }
    }
}

// TWO buckets per warp: 16-lane sub-warp bitonic for n<=16 (99.6% of buckets)
__global__ void bucket_emit_kernel(float* __restrict__ out, int E) {
    int gw   = (blockIdx.x * blockDim.x + threadIdx.x) >> 5;
    int lane = threadIdx.x & 31;
    unsigned int b0 = (unsigned int)gw * 2u;
    if (b0 >= NB) return;
    unsigned int start0 = (b0 == 0u) ? 0u : g_incl[b0 - 1];
    unsigned int end0   = g_incl[b0];
    unsigned int end1   = g_incl[b0 + 1];
    unsigned int n0 = end0 - start0, n1 = end1 - end0;
    if ((n0 | n1) == 0u) return;
    int is64 = g_is64;
    int sh = is64 ? 13 : 12;

    if (n0 <= 16u && n1 <= 16u) {
        int half = lane >> 4, l = lane & 15;
        unsigned int start  = half ? end0 : start0;
        unsigned int n      = half ? n1 : n0;
        unsigned int bucket = b0 + (unsigned int)half;
        unsigned int v = ((unsigned int)l < n) ? (unsigned int)g_low[start + l]
                                               : 0xFFFFFFFFu;
        #pragma unroll
        for (unsigned int k = 2; k <= 16; k <<= 1) {
            for (unsigned int j = k >> 1; j > 0; j >>= 1) {
                unsigned int o = __shfl_xor_sync(0xFFFFFFFFu, v, j);
                bool dirUp = (((unsigned int)l & k) == 0);
                bool lower = (((unsigned int)l & j) == 0);
                unsigned int mn = v < o ? v : o, mx = v < o ? o : v;
                v = (lower == dirUp) ? mn : mx;
            }
        }
        unsigned int prev = __shfl_up_sync(0xFFFFFFFFu, v, 1);
        if ((unsigned int)l < n) {
            bool first = (l == 0) || (v != prev);
            emit_pos(out, E, bucket, sh, is64, v, first,
                     (long long)(start + (unsigned int)l));
        }
    } else {
        if (n0) emit_bucket_fullwarp(out, E, b0,     start0, n0, sh, is64, lane);
        if (n1) emit_bucket_fullwarp(out, E, b0 + 1, end0,   n1, sh, is64, lane);
    }
}

__global__ void finalize_kernel(float* __restrict__ out) {
    int i = blockIdx.x * blockDim.x + threadIdx.x;
    if (i >= KC * DIM) return;
    {
        int c = i >> 6;     // i / DIM
        float v = (g_counts[c] > 0u) ? dec_f32(g_xmax[i]) : 0.0f;
        out[i] = v;
    }
    if (i < KC * 3) {
        int c = i / 3;
        unsigned int cnt = g_counts[c];
        out[OFF_POS + i] = g_possum[i] / (float)(cnt > 0u ? cnt : 1u);
    }
    if (i < KC) {
        out[OFF_BATCH + i] = (float)(i / (NV0 * NV1));
        out[OFF_MASK + i]  = (g_counts[i] > 0u) ? 1.0f : 0.0f;
    }
}

// ---------------------------------------------------------------------------
// Launch: fork-join; submission order makes edgekey the 4th launch (profiled)
// ---------------------------------------------------------------------------
extern "C" void kernel_launch(void* const* d_in, const int* in_sizes, int n_in,
                              void* d_out, int out_size) {
    int ib = 0;
    for (int i = 1; i < n_in && i < 4; i++)
        if (in_sizes[i] < in_sizes[ib]) ib = i;
    long long N = in_sizes[ib];
    int ix = -1, ip = -1, ie = -1;
    for (int i = 0; i < n_in && i < 4; i++) {
        if (i == ib) continue;
        long long s = in_sizes[i];
        if (s == 64 * N)     ix = i;
        else if (s == 3 * N) ip = i;
        else                 ie = i;
    }
    if (ix < 0 || ip < 0 || ie < 0) { ix = 0; ip = 1; ib = 2; ie = 3; }

    const float* x    = (const float*)d_in[ix];
    const float* pos  = (const float*)d_in[ip];
    const void*  bat  = d_in[ib];
    const void*  eidx = d_in[ie];
    float*       out  = (float*)d_out;

    int Ni = (int)N;
    int E  = in_sizes[ie] / 2;
    if (Ni > N_MAX) Ni = N_MAX;
    if (E > E_MAX)  E  = E_MAX;

    static cudaStream_t s1 = nullptr;
    static cudaEvent_t evFork = nullptr, evJoin = nullptr;
    if (!s1) {
        cudaStreamCreateWithFlags(&s1, cudaStreamNonBlocking);
        cudaEventCreateWithFlags(&evFork, cudaEventDisableTiming);
        cudaEventCreateWithFlags(&evJoin, cudaEventDisableTiming);
    }

    const int T = 256;
    init_kernel<<<(KC * DIM / 4 + T - 1) / T, T>>>((const unsigned int*)eidx);     // 1
    cluster_kernel<<<(Ni + T - 1) / T, T>>>(pos, bat, Ni);                          // 2

    // fork: side stream runs xmax now, finalize later
    cudaEventRecord(evFork, 0);
    cudaStreamWaitEvent(s1, evFork, 0);
    xmax_kernel<<<(int)(((size_t)Ni * 32 + T - 1) / T), T, 0, s1>>>(x, Ni);        // 3

    edgekey_kernel<<<(E + T - 1) / T, T>>>(eidx, Ni, E);                            // 4 <- profiled
    scan1_kernel<<<NBLK, 1024>>>();                                                 // 5
    scan2_kernel<<<1, 1024>>>();                                                    // 6
    scan3_kernel<<<NB / 1024, 1024>>>();                                            // 7
    scatter_kernel<<<(E + T - 1) / T, T>>>(eidx, Ni, E);                            // 8
    bucket_emit_kernel<<<NB / 16, T>>>(out, E);                                     // 9

    finalize_kernel<<<(KC * DIM + T - 1) / T, T, 0, s1>>>(out);                     // 10
    cudaEventRecord(evJoin, s1);
    cudaStreamWaitEvent(0, evJoin, 0);
    (void)out_size;
}

// round 14
// speedup vs baseline: 1.0646x; 1.0303x over previous
#include <cuda_runtime.h>
#include <stdint.h>

// ---------------------------------------------------------------------------
// Problem constants (DSEC 480x640, 4x4 voxels, B=4)
// ---------------------------------------------------------------------------
#define NV0 120
#define NV1 160
#define NBATCH 4
#define KC (NBATCH * NV0 * NV1)   /* 76800 */
#define DIM 64

#define N_MAX (1 << 20)
#define E_MAX (1 << 23)
#define NB (1 << 20)              /* sort buckets */
#define NBLK (NB / 1024)
#define CAP 64                    /* slab capacity per bucket */
#define ENC_NEG_INF 0x007FFFFFu

// int32-wrapped sentinel: (int32)(76800*76800) = 1603272704
#define SENT32 1603272704
#define SENT64 5898240000ull
// biased (unsigned-order) sentinel: SENT32 ^ 0x80000000 (4096-aligned: low=0)
#define USENT32 3750756352u
#define SENTB32 (USENT32 >> 12)        /* 915712 */
#define SENTB64 ((unsigned)(SENT64 >> 13))  /* 720000 */

// Output layout (float32 flatten, reference return order):
#define OFF_POS   (KC * DIM)
#define OFF_BATCH (OFF_POS + KC * 3)
#define OFF_MASK  (OFF_BATCH + KC)
#define OFF_EI    (OFF_MASK + KC)

// ---------------------------------------------------------------------------
// Static device scratch
// ---------------------------------------------------------------------------
__device__ int            g_is64;
__device__ unsigned int   g_sent;            // sentinel (self-loop) edge count
__device__ int            g_cluster[N_MAX];
__device__ unsigned int   g_counts[KC];
__device__ float          g_possum[KC * 3];
__device__ unsigned int   g_xmax[KC * DIM];
__device__ unsigned short g_slab[(size_t)NB * CAP];  // 128MB bucket slabs
__device__ unsigned int   g_bcnt[NB];        // per-bucket stored counts
__device__ unsigned int   g_incl[NB];        // inclusive scan (incl. sentinels)
__device__ unsigned int   g_bsum[NBLK];

__device__ __forceinline__ unsigned int enc_f32(float v) {
    unsigned int u = __float_as_uint(v);
    return (u & 0x80000000u) ? ~u : (u | 0x80000000u);
}
__device__ __forceinline__ float dec_f32(unsigned int u) {
    u = (u & 0x80000000u) ? (u & 0x7FFFFFFFu) : ~u;
    return __uint_as_float(u);
}
__device__ __forceinline__ int ld_id(const void* p, long long i, int is64) {
    return is64 ? (int)((const long long*)p)[i] : ((const int*)p)[i];
}
__device__ __forceinline__ int clampi(int v, int lo, int hi) {
    return v < lo ? lo : (v > hi ? hi : v);
}

// i32 key from clusters (biased unsigned order); sc==dc gives exactly USENT32
__device__ __forceinline__ unsigned int edge_k32(int sc, int dc) {
    int key32 = (sc == dc) ? SENT32
              : (int)((unsigned int)sc * 76800u + (unsigned int)dc);
    return ((unsigned int)key32) ^ 0x80000000u;
}
// i64 biased key (exact)
__device__ __forceinline__ unsigned long long edge_uk64(int sc, int dc) {
    if (sc == dc) return SENT64;
    return (unsigned long long)(unsigned int)sc * 76800ull
         + (unsigned long long)(unsigned int)dc;
}

// i32 decode via magic division. 76800 = 2^10*75; floor-div fixup 2^31 = 76800*27962+2048
__device__ __forceinline__ void decode32(unsigned int uk,
                                         float* sf, float* df, bool* valid) {
    *valid = (uk < USENT32);
    unsigned int q = __umulhi(uk >> 10, 57266231u);
    unsigned int r = uk - q * 76800u;
    int qf; unsigned int rf;
    if (r >= 2048u) { qf = (int)q - 27962; rf = r - 2048u; }
    else            { qf = (int)q - 27963; rf = r + 74752u; }
    *sf = (float)qf;
    *df = (float)rf;
}
__device__ __forceinline__ void decode_key(unsigned long long uk, int is64,
                                           float* sf, float* df, bool* valid) {
    if (is64) {
        *valid = (uk < SENT64);
        *sf = (float)(long long)(uk / 76800ull);
        *df = (float)(long long)(uk % 76800ull);
    } else {
        decode32((unsigned int)uk, sf, df, valid);
    }
}

__device__ __forceinline__ void emit_pos(float* __restrict__ out, int E,
                                         unsigned int bucket,
                                         int sh, int is64, unsigned int v,
                                         bool first, long long p) {
    const long long off_ei = OFF_EI;
    const long long off_em = off_ei + 2ll * E;
    unsigned long long uk = (((unsigned long long)bucket) << sh) | v;
    float sf, df; bool valid;
    decode_key(uk, is64, &sf, &df, &valid);
    bool mask = first && valid;
    out[off_ei + p]     = mask ? sf   : -1.0f;
    out[off_ei + E + p] = mask ? df   : -1.0f;
    out[off_em + p]     = mask ? 1.0f : 0.0f;
}

// ---------------------------------------------------------------------------
// init (+ dtype sniff): vectorized uint4 stores
// ---------------------------------------------------------------------------
__global__ void init_kernel(const unsigned int* ew) {
    int i = blockIdx.x * blockDim.x + threadIdx.x;
    if (i == 0) {
        unsigned int o = 0;
        for (int k = 1; k < 128; k += 2) o |= ew[k];
        g_is64 = (o == 0u) ? 1 : 0;
        g_sent = 0u;
    }
    if (i >= KC * DIM / 4) return;
    ((uint4*)g_xmax)[i] = make_uint4(ENC_NEG_INF, ENC_NEG_INF, ENC_NEG_INF, ENC_NEG_INF);
    if (i < KC / 4)     ((uint4*)g_counts)[i] = make_uint4(0u, 0u, 0u, 0u);
    if (i < KC * 3 / 4) ((uint4*)g_possum)[i] = make_uint4(0u, 0u, 0u, 0u);
    if (i < NB / 4)     ((uint4*)g_bcnt)[i]   = make_uint4(0u, 0u, 0u, 0u);
}

// ---------------------------------------------------------------------------
// cluster: one thread per node
// ---------------------------------------------------------------------------
__global__ void cluster_kernel(const float* __restrict__ pos,
                               const void* batch, int N) {
    int i = blockIdx.x * blockDim.x + threadIdx.x;
    if (i >= N) return;
    int is64 = g_is64;
    float p0 = pos[3 * i + 0];
    float p1 = pos[3 * i + 1];
    float p2 = pos[3 * i + 2];
    int c0 = clampi((int)floorf(p1 * 0.25f), 0, NV0 - 1);
    int c1 = clampi((int)floorf(p2 * 0.25f), 0, NV1 - 1);
    int b  = clampi(ld_id(batch, i, is64), 0, NBATCH - 1);
    int c  = c0 + c1 * NV0 + b * (NV0 * NV1);
    g_cluster[i] = c;
    atomicAdd(&g_counts[c], 1u);
    atomicAdd(&g_possum[3 * c + 0], p0);
    atomicAdd(&g_possum[3 * c + 1], p1);
    atomicAdd(&g_possum[3 * c + 2], p2);
}

// x scatter-max: round-7 proven form
__global__ void xmax_kernel(const float* __restrict__ x, int N) {
    int gw   = (blockIdx.x * blockDim.x + threadIdx.x) >> 5;
    int lane = threadIdx.x & 31;
    if (gw >= N) return;
    int c = g_cluster[gw];
    float2 v = ((const float2*)(x + (size_t)gw * DIM))[lane];
    unsigned int* dst = g_xmax + (size_t)c * DIM;
    atomicMax(&dst[2 * lane],     enc_f32(v.x));
    atomicMax(&dst[2 * lane + 1], enc_f32(v.y));
}

// ---------------------------------------------------------------------------
// FUSED edge pass: gather clusters -> key -> count+store into bucket slab.
// Sentinel keys (low = 0 by construction) are counted only, never stored.
// ---------------------------------------------------------------------------
__device__ __forceinline__ void place32(unsigned int k) {
    if (k == USENT32) {
        atomicAdd(&g_sent, 1u);
    } else {
        unsigned int b = k >> 12;
        unsigned int pos = atomicAdd(&g_bcnt[b], 1u);
        if (pos < CAP) g_slab[(size_t)b * CAP + pos] = (unsigned short)(k & 0xFFFu);
    }
}

__global__ void edge_fused_kernel(const void* eidx, int N, int E) {
    int t = blockIdx.x * blockDim.x + threadIdx.x;
    int is64 = g_is64;
    if (!is64) {
        if ((E & 3) == 0) {
            int nq = E >> 2;
            if (t >= nq) return;
            int4 uu = ((const int4*)eidx)[t];
            int4 vv = ((const int4*)((const int*)eidx + E))[t];
            int sc0 = g_cluster[clampi(uu.x, 0, N - 1)];
            int sc1 = g_cluster[clampi(uu.y, 0, N - 1)];
            int sc2 = g_cluster[clampi(uu.z, 0, N - 1)];
            int sc3 = g_cluster[clampi(uu.w, 0, N - 1)];
            int dc0 = g_cluster[clampi(vv.x, 0, N - 1)];
            int dc1 = g_cluster[clampi(vv.y, 0, N - 1)];
            int dc2 = g_cluster[clampi(vv.z, 0, N - 1)];
            int dc3 = g_cluster[clampi(vv.w, 0, N - 1)];
            place32(edge_k32(sc0, dc0));
            place32(edge_k32(sc1, dc1));
            place32(edge_k32(sc2, dc2));
            place32(edge_k32(sc3, dc3));
        } else {
            if (t >= E) return;
            int u = clampi(((const int*)eidx)[t], 0, N - 1);
            int v = clampi(((const int*)eidx)[(size_t)E + t], 0, N - 1);
            place32(edge_k32(g_cluster[u], g_cluster[v]));
        }
    } else {
        if (t >= E) return;
        int u = clampi(ld_id(eidx, t, 1), 0, N - 1);
        int v = clampi(ld_id(eidx, (long long)E + t, 1), 0, N - 1);
        unsigned long long uk = edge_uk64(g_cluster[u], g_cluster[v]);
        if (uk == SENT64) {
            atomicAdd(&g_sent, 1u);
        } else {
            unsigned int b = (unsigned int)(uk >> 13);
            unsigned int pos = atomicAdd(&g_bcnt[b], 1u);
            if (pos < CAP)
                g_slab[(size_t)b * CAP + pos] = (unsigned short)(uk & 0x1FFFu);
        }
    }
}

// -- shfl-based scans (totals include sentinel count at the sentinel bucket) --
__device__ __forceinline__ unsigned int blk_incl_scan_1024(unsigned int v,
                                                           unsigned int* wsum) {
    int t = threadIdx.x;
    #pragma unroll
    for (int d = 1; d < 32; d <<= 1) {
        unsigned int u = __shfl_up_sync(0xFFFFFFFFu, v, d);
        if ((t & 31) >= d) v += u;
    }
    if ((t & 31) == 31) wsum[t >> 5] = v;
    __syncthreads();
    if (t < 32) {
        unsigned int s = wsum[t];
        #pragma unroll
        for (int d = 1; d < 32; d <<= 1) {
            unsigned int u = __shfl_up_sync(0xFFFFFFFFu, s, d);
            if (t >= d) s += u;
        }
        wsum[t] = s;
    }
    __syncthreads();
    if (t >= 32) v += wsum[(t >> 5) - 1];
    return v;
}

__global__ void scan1_kernel() {
    __shared__ unsigned int wsum[32];
    int i = blockIdx.x * 1024 + threadIdx.x;
    unsigned int sb = g_is64 ? SENTB64 : SENTB32;
    unsigned int c = g_bcnt[i] + ((unsigned int)i == sb ? g_sent : 0u);
    unsigned int v = blk_incl_scan_1024(c, wsum);
    g_incl[i] = v;
    if (threadIdx.x == 1023) g_bsum[blockIdx.x] = v;
}
__global__ void scan2_kernel() {
    __shared__ unsigned int wsum[32];
    unsigned int orig = g_bsum[threadIdx.x];
    unsigned int v = blk_incl_scan_1024(orig, wsum);
    g_bsum[threadIdx.x] = v - orig;   // exclusive
}
__global__ void scan3_kernel() {
    int i = blockIdx.x * blockDim.x + threadIdx.x;
    if (i >= NB) return;
    g_incl[i] += g_bsum[i >> 10];
}

// ---------------------------------------------------------------------------
// emit: n<=32 warp bitonic from slab; 32<n<=CAP odd-even; sentinel special
// ---------------------------------------------------------------------------
__device__ void emit_run_bitonic(float* __restrict__ out, int E,
                                 unsigned int bucket, const unsigned short* row,
                                 long long base, unsigned int n,
                                 int sh, int is64, int lane) {
    unsigned int v = (lane < (int)n) ? (unsigned int)row[lane] : 0xFFFFFFFFu;
    #pragma unroll
    for (unsigned int k = 2; k <= 32; k <<= 1) {
        for (unsigned int j = k >> 1; j > 0; j >>= 1) {
            unsigned int o = __shfl_xor_sync(0xFFFFFFFFu, v, j);
            bool dirUp = ((lane & k) == 0);
            bool lower = ((lane & j) == 0);
            unsigned int mn = v < o ? v : o, mx = v < o ? o : v;
            v = (lower == dirUp) ? mn : mx;
        }
    }
    unsigned int prev = __shfl_up_sync(0xFFFFFFFFu, v, 1);
    if (lane < (int)n) {
        bool first = (lane == 0) || (v != prev);
        emit_pos(out, E, bucket, sh, is64, v, first, base + lane);
    }
}

__device__ void emit_run_oddeven(float* __restrict__ out, int E,
                                 unsigned int bucket, unsigned short* a,
                                 long long base, unsigned int n,
                                 int sh, int is64, int lane) {
    for (unsigned int pass = 0; pass < n; ++pass) {
        unsigned int st = pass & 1u;
        for (unsigned int i = st + 2u * lane; i + 1 < n; i += 64u) {
            unsigned short x0 = a[i], x1 = a[i + 1];
            if (x0 > x1) { a[i] = x1; a[i + 1] = x0; }
        }
        __syncwarp();
    }
    for (unsigned int i = lane; i < n; i += 32) {
        unsigned int v = a[i];
        bool first = (i == 0) || (v != (unsigned int)a[i - 1]);
        emit_pos(out, E, bucket, sh, is64, v, first, base + i);
    }
}

__device__ void emit_bucket(float* __restrict__ out, int E, unsigned int bucket,
                            unsigned int startpos, unsigned int n,
                            int sh, int is64, int lane, unsigned int sentb) {
    unsigned short* row = g_slab + (size_t)bucket * CAP;
    if (bucket == sentb) {
        unsigned int S = g_sent;
        if (S > n) S = n;
        unsigned int stored = n - S;
        // sentinel run: low=0 sorts first; uk==USENT -> invalid -> all masked
        const long long off_ei = OFF_EI;
        const long long off_em = off_ei + 2ll * E;
        for (unsigned int i = lane; i < S; i += 32) {
            long long p = (long long)(startpos + i);
            out[off_ei + p]     = -1.0f;
            out[off_ei + E + p] = -1.0f;
            out[off_em + p]     = 0.0f;
        }
        if (stored == 0) return;
        long long base = (long long)(startpos + S);
        if (stored <= 32) emit_run_bitonic(out, E, bucket, row, base, stored, sh, is64, lane);
        else              emit_run_oddeven(out, E, bucket, row, base,
                                           stored > CAP ? CAP : stored, sh, is64, lane);
        return;
    }
    if (n <= 32) emit_run_bitonic(out, E, bucket, row, (long long)startpos, n, sh, is64, lane);
    else         emit_run_oddeven(out, E, bucket, row, (long long)startpos,
                                  n > CAP ? CAP : n, sh, is64, lane);
}

// TWO buckets per warp: 16-lane sub-warp bitonic for n<=16 (common case)
__global__ void bucket_emit_kernel(float* __restrict__ out, int E) {
    int gw   = (blockIdx.x * blockDim.x + threadIdx.x) >> 5;
    int lane = threadIdx.x & 31;
    unsigned int b0 = (unsigned int)gw * 2u;
    if (b0 >= NB) return;
    unsigned int start0 = (b0 == 0u) ? 0u : g_incl[b0 - 1];
    unsigned int end0   = g_incl[b0];
    unsigned int end1   = g_incl[b0 + 1];
    unsigned int n0 = end0 - start0, n1 = end1 - end0;
    if ((n0 | n1) == 0u) return;
    int is64 = g_is64;
    int sh = is64 ? 13 : 12;
    unsigned int sentb = is64 ? SENTB64 : SENTB32;

    if (n0 <= 16u && n1 <= 16u && b0 != sentb && b0 + 1 != sentb) {
        int half = lane >> 4, l = lane & 15;
        unsigned int start  = half ? end0 : start0;
        unsigned int n      = half ? n1 : n0;
        unsigned int bucket = b0 + (unsigned int)half;
        const unsigned short* row = g_slab + (size_t)bucket * CAP;
        unsigned int v = ((unsigned int)l < n) ? (unsigned int)row[l] : 0xFFFFFFFFu;
        #pragma unroll
        for (unsigned int k = 2; k <= 16; k <<= 1) {
            for (unsigned int j = k >> 1; j > 0; j >>= 1) {
                unsigned int o = __shfl_xor_sync(0xFFFFFFFFu, v, j);
                bool dirUp = (((unsigned int)l & k) == 0);
                bool lower = (((unsigned int)l & j) == 0);
                unsigned int mn = v < o ? v : o, mx = v < o ? o : v;
                v = (lower == dirUp) ? mn : mx;
            }
        }
        unsigned int prev = __shfl_up_sync(0xFFFFFFFFu, v, 1);
        if ((unsigned int)l < n) {
            bool first = (l == 0) || (v != prev);
            emit_pos(out, E, bucket, sh, is64, v, first,
                     (long long)(start + (unsigned int)l));
        }
    } else {
        if (n0) emit_bucket(out, E, b0,     start0, n0, sh, is64, lane, sentb);
        if (n1) emit_bucket(out, E, b0 + 1, end0,   n1, sh, is64, lane, sentb);
    }
}

__global__ void finalize_kernel(float* __restrict__ out) {
    int i = blockIdx.x * blockDim.x + threadIdx.x;
    if (i >= KC * DIM) return;
    {
        int c = i >> 6;
        float v = (g_counts[c] > 0u) ? dec_f32(g_xmax[i]) : 0.0f;
        out[i] = v;
    }
    if (i < KC * 3) {
        int c = i / 3;
        unsigned int cnt = g_counts[c];
        out[OFF_POS + i] = g_possum[i] / (float)(cnt > 0u ? cnt : 1u);
    }
    if (i < KC) {
        out[OFF_BATCH + i] = (float)(i / (NV0 * NV1));
        out[OFF_MASK + i]  = (g_counts[i] > 0u) ? 1.0f : 0.0f;
    }
}

// ---------------------------------------------------------------------------
// Launch: fork-join; fused edge pass is the 4th launch (profiled next round)
// ---------------------------------------------------------------------------
extern "C" void kernel_launch(void* const* d_in, const int* in_sizes, int n_in,
                              void* d_out, int out_size) {
    int ib = 0;
    for (int i = 1; i < n_in && i < 4; i++)
        if (in_sizes[i] < in_sizes[ib]) ib = i;
    long long N = in_sizes[ib];
    int ix = -1, ip = -1, ie = -1;
    for (int i = 0; i < n_in && i < 4; i++) {
        if (i == ib) continue;
        long long s = in_sizes[i];
        if (s == 64 * N)     ix = i;
        else if (s == 3 * N) ip = i;
        else                 ie = i;
    }
    if (ix < 0 || ip < 0 || ie < 0) { ix = 0; ip = 1; ib = 2; ie = 3; }

    const float* x    = (const float*)d_in[ix];
    const float* pos  = (const float*)d_in[ip];
    const void*  bat  = d_in[ib];
    const void*  eidx = d_in[ie];
    float*       out  = (float*)d_out;

    int Ni = (int)N;
    int E  = in_sizes[ie] / 2;
    if (Ni > N_MAX) Ni = N_MAX;
    if (E > E_MAX)  E  = E_MAX;

    static cudaStream_t s1 = nullptr;
    static cudaEvent_t evFork = nullptr, evJoin = nullptr;
    if (!s1) {
        cudaStreamCreateWithFlags(&s1, cudaStreamNonBlocking);
        cudaEventCreateWithFlags(&evFork, cudaEventDisableTiming);
        cudaEventCreateWithFlags(&evJoin, cudaEventDisableTiming);
    }

    const int T = 256;
    init_kernel<<<(KC * DIM / 4 + T - 1) / T, T>>>((const unsigned int*)eidx);  // 1
    cluster_kernel<<<(Ni + T - 1) / T, T>>>(pos, bat, Ni);                       // 2

    // fork: side stream runs xmax now, finalize later
    cudaEventRecord(evFork, 0);
    cudaStreamWaitEvent(s1, evFork, 0);
    xmax_kernel<<<(int)(((size_t)Ni * 32 + T - 1) / T), T, 0, s1>>>(x, Ni);     // 3

    edge_fused_kernel<<<(E + T - 1) / T, T>>>(eidx, Ni, E);                      // 4 <- profiled
    scan1_kernel<<<NBLK, 1024>>>();                                              // 5
    scan2_kernel<<<1, 1024>>>();                                                 // 6
    scan3_kernel<<<NB / 1024, 1024>>>();                                         // 7
    bucket_emit_kernel<<<NB / 16, T>>>(out, E);                                  // 8

    finalize_kernel<<<(KC * DIM + T - 1) / T, T, 0, s1>>>(out);                  // 9
    cudaEventRecord(evJoin, s1);
    cudaStreamWaitEvent(0, evJoin, 0);
    (void)out_size;
}

// round 15
// speedup vs baseline: 1.0900x; 1.0239x over previous
#include <cuda_runtime.h>
#include <stdint.h>

// ---------------------------------------------------------------------------
// Problem constants (DSEC 480x640, 4x4 voxels, B=4)
// ---------------------------------------------------------------------------
#define NV0 120
#define NV1 160
#define NBATCH 4
#define KC (NBATCH * NV0 * NV1)   /* 76800 */
#define DIM 64

#define N_MAX (1 << 20)
#define E_MAX (1 << 23)
#define NB (1 << 20)              /* sort buckets */
#define NBLK (NB / 1024)
#define CAP 32                    /* slab capacity per bucket (64MB, L2-resident) */
#define OCAP 8192                 /* overflow list capacity */
#define MBUF 128                  /* per-warp merge buffer */
#define ENC_NEG_INF 0x007FFFFFu

// int32-wrapped sentinel: (int32)(76800*76800) = 1603272704
#define SENT32 1603272704
#define SENT64 5898240000ull
// biased (unsigned-order) sentinel: SENT32 ^ 0x80000000 (4096-aligned: low=0)
#define USENT32 3750756352u
#define SENTB32 (USENT32 >> 12)        /* 915712 */
#define SENTB64 ((unsigned)(SENT64 >> 13))  /* 720000 */

// Output layout (float32 flatten, reference return order):
#define OFF_POS   (KC * DIM)
#define OFF_BATCH (OFF_POS + KC * 3)
#define OFF_MASK  (OFF_BATCH + KC)
#define OFF_EI    (OFF_MASK + KC)

// ---------------------------------------------------------------------------
// Static device scratch
// ---------------------------------------------------------------------------
__device__ int            g_is64;
__device__ unsigned int   g_sent;            // sentinel (self-loop) edge count
__device__ unsigned int   g_ocnt;            // overflow entries
__device__ int            g_cluster[N_MAX];
__device__ unsigned int   g_counts[KC];
__device__ float          g_possum[KC * 3];
__device__ unsigned int   g_xmax[KC * DIM];
__device__ unsigned short g_slab[(size_t)NB * CAP];  // 64MB bucket slabs
__device__ unsigned long long g_oflow[OCAP];         // spilled full keys
__device__ unsigned int   g_bcnt[NB];        // per-bucket total counts
__device__ unsigned int   g_incl[NB];        // inclusive scan (incl. sentinels)
__device__ unsigned int   g_bsum[NBLK];

__device__ __forceinline__ unsigned int enc_f32(float v) {
    unsigned int u = __float_as_uint(v);
    return (u & 0x80000000u) ? ~u : (u | 0x80000000u);
}
__device__ __forceinline__ float dec_f32(unsigned int u) {
    u = (u & 0x80000000u) ? (u & 0x7FFFFFFFu) : ~u;
    return __uint_as_float(u);
}
__device__ __forceinline__ int ld_id(const void* p, long long i, int is64) {
    return is64 ? (int)((const long long*)p)[i] : ((const int*)p)[i];
}
__device__ __forceinline__ int clampi(int v, int lo, int hi) {
    return v < lo ? lo : (v > hi ? hi : v);
}

// i32 key from clusters (biased unsigned order); sc==dc gives exactly USENT32
__device__ __forceinline__ unsigned int edge_k32(int sc, int dc) {
    int key32 = (sc == dc) ? SENT32
              : (int)((unsigned int)sc * 76800u + (unsigned int)dc);
    return ((unsigned int)key32) ^ 0x80000000u;
}
__device__ __forceinline__ unsigned long long edge_uk64(int sc, int dc) {
    if (sc == dc) return SENT64;
    return (unsigned long long)(unsigned int)sc * 76800ull
         + (unsigned long long)(unsigned int)dc;
}

// i32 decode via magic division. 76800 = 2^10*75; floor-div fixup 2^31 = 76800*27962+2048
__device__ __forceinline__ void decode32(unsigned int uk,
                                         float* sf, float* df, bool* valid) {
    *valid = (uk < USENT32);
    unsigned int q = __umulhi(uk >> 10, 57266231u);
    unsigned int r = uk - q * 76800u;
    int qf; unsigned int rf;
    if (r >= 2048u) { qf = (int)q - 27962; rf = r - 2048u; }
    else            { qf = (int)q - 27963; rf = r + 74752u; }
    *sf = (float)qf;
    *df = (float)rf;
}
__device__ __forceinline__ void decode_key(unsigned long long uk, int is64,
                                           float* sf, float* df, bool* valid) {
    if (is64) {
        *valid = (uk < SENT64);
        *sf = (float)(long long)(uk / 76800ull);
        *df = (float)(long long)(uk % 76800ull);
    } else {
        decode32((unsigned int)uk, sf, df, valid);
    }
}

__device__ __forceinline__ void emit_pos(float* __restrict__ out, int E,
                                         unsigned int bucket,
                                         int sh, int is64, unsigned int v,
                                         bool first, long long p) {
    const long long off_ei = OFF_EI;
    const long long off_em = off_ei + 2ll * E;
    unsigned long long uk = (((unsigned long long)bucket) << sh) | v;
    float sf, df; bool valid;
    decode_key(uk, is64, &sf, &df, &valid);
    bool mask = first && valid;
    out[off_ei + p]     = mask ? sf   : -1.0f;
    out[off_ei + E + p] = mask ? df   : -1.0f;
    out[off_em + p]     = mask ? 1.0f : 0.0f;
}

// ---------------------------------------------------------------------------
// init (+ dtype sniff): vectorized uint4 stores
// ---------------------------------------------------------------------------
__global__ void init_kernel(const unsigned int* ew) {
    int i = blockIdx.x * blockDim.x + threadIdx.x;
    if (i == 0) {
        unsigned int o = 0;
        for (int k = 1; k < 128; k += 2) o |= ew[k];
        g_is64 = (o == 0u) ? 1 : 0;
        g_sent = 0u;
        g_ocnt = 0u;
    }
    if (i >= KC * DIM / 4) return;
    ((uint4*)g_xmax)[i] = make_uint4(ENC_NEG_INF, ENC_NEG_INF, ENC_NEG_INF, ENC_NEG_INF);
    if (i < KC / 4)     ((uint4*)g_counts)[i] = make_uint4(0u, 0u, 0u, 0u);
    if (i < KC * 3 / 4) ((uint4*)g_possum)[i] = make_uint4(0u, 0u, 0u, 0u);
    if (i < NB / 4)     ((uint4*)g_bcnt)[i]   = make_uint4(0u, 0u, 0u, 0u);
}

// ---------------------------------------------------------------------------
// cluster: one thread per node
// ---------------------------------------------------------------------------
__global__ void cluster_kernel(const float* __restrict__ pos,
                               const void* batch, int N) {
    int i = blockIdx.x * blockDim.x + threadIdx.x;
    if (i >= N) return;
    int is64 = g_is64;
    float p0 = pos[3 * i + 0];
    float p1 = pos[3 * i + 1];
    float p2 = pos[3 * i + 2];
    int c0 = clampi((int)floorf(p1 * 0.25f), 0, NV0 - 1);
    int c1 = clampi((int)floorf(p2 * 0.25f), 0, NV1 - 1);
    int b  = clampi(ld_id(batch, i, is64), 0, NBATCH - 1);
    int c  = c0 + c1 * NV0 + b * (NV0 * NV1);
    g_cluster[i] = c;
    atomicAdd(&g_counts[c], 1u);
    atomicAdd(&g_possum[3 * c + 0], p0);
    atomicAdd(&g_possum[3 * c + 1], p1);
    atomicAdd(&g_possum[3 * c + 2], p2);
}

// x scatter-max: round-7 proven form
__global__ void xmax_kernel(const float* __restrict__ x, int N) {
    int gw   = (blockIdx.x * blockDim.x + threadIdx.x) >> 5;
    int lane = threadIdx.x & 31;
    if (gw >= N) return;
    int c = g_cluster[gw];
    float2 v = ((const float2*)(x + (size_t)gw * DIM))[lane];
    unsigned int* dst = g_xmax + (size_t)c * DIM;
    atomicMax(&dst[2 * lane],     enc_f32(v.x));
    atomicMax(&dst[2 * lane + 1], enc_f32(v.y));
}

// ---------------------------------------------------------------------------
// FUSED edge pass: gather clusters -> key -> count+store into bucket slab.
// Sentinel keys counted only; slab overflow spills the full key.
// ---------------------------------------------------------------------------
__device__ __forceinline__ void place32(unsigned int k) {
    if (k == USENT32) {
        atomicAdd(&g_sent, 1u);
    } else {
        unsigned int b = k >> 12;
        unsigned int pos = atomicAdd(&g_bcnt[b], 1u);
        if (pos < CAP) {
            g_slab[(size_t)b * CAP + pos] = (unsigned short)(k & 0xFFFu);
        } else {
            unsigned int o = atomicAdd(&g_ocnt, 1u);
            if (o < OCAP) g_oflow[o] = (unsigned long long)k;
        }
    }
}

__global__ void edge_fused_kernel(const void* eidx, int N, int E) {
    int t = blockIdx.x * blockDim.x + threadIdx.x;
    int is64 = g_is64;
    if (!is64) {
        if ((E & 3) == 0) {
            int nq = E >> 2;
            if (t >= nq) return;
            int4 uu = ((const int4*)eidx)[t];
            int4 vv = ((const int4*)((const int*)eidx + E))[t];
            int sc0 = g_cluster[clampi(uu.x, 0, N - 1)];
            int sc1 = g_cluster[clampi(uu.y, 0, N - 1)];
            int sc2 = g_cluster[clampi(uu.z, 0, N - 1)];
            int sc3 = g_cluster[clampi(uu.w, 0, N - 1)];
            int dc0 = g_cluster[clampi(vv.x, 0, N - 1)];
            int dc1 = g_cluster[clampi(vv.y, 0, N - 1)];
            int dc2 = g_cluster[clampi(vv.z, 0, N - 1)];
            int dc3 = g_cluster[clampi(vv.w, 0, N - 1)];
            place32(edge_k32(sc0, dc0));
            place32(edge_k32(sc1, dc1));
            place32(edge_k32(sc2, dc2));
            place32(edge_k32(sc3, dc3));
        } else {
            if (t >= E) return;
            int u = clampi(((const int*)eidx)[t], 0, N - 1);
            int v = clampi(((const int*)eidx)[(size_t)E + t], 0, N - 1);
            place32(edge_k32(g_cluster[u], g_cluster[v]));
        }
    } else {
        if (t >= E) return;
        int u = clampi(ld_id(eidx, t, 1), 0, N - 1);
        int v = clampi(ld_id(eidx, (long long)E + t, 1), 0, N - 1);
        unsigned long long uk = edge_uk64(g_cluster[u], g_cluster[v]);
        if (uk == SENT64) {
            atomicAdd(&g_sent, 1u);
        } else {
            unsigned int b = (unsigned int)(uk >> 13);
            unsigned int pos = atomicAdd(&g_bcnt[b], 1u);
            if (pos < CAP) {
                g_slab[(size_t)b * CAP + pos] = (unsigned short)(uk & 0x1FFFu);
            } else {
                unsigned int o = atomicAdd(&g_ocnt, 1u);
                if (o < OCAP) g_oflow[o] = uk;
            }
        }
    }
}

// -- shfl-based scans (totals include sentinel count at the sentinel bucket) --
__device__ __forceinline__ unsigned int blk_incl_scan_1024(unsigned int v,
                                                           unsigned int* wsum) {
    int t = threadIdx.x;
    #pragma unroll
    for (int d = 1; d < 32; d <<= 1) {
        unsigned int u = __shfl_up_sync(0xFFFFFFFFu, v, d);
        if ((t & 31) >= d) v += u;
    }
    if ((t & 31) == 31) wsum[t >> 5] = v;
    __syncthreads();
    if (t < 32) {
        unsigned int s = wsum[t];
        #pragma unroll
        for (int d = 1; d < 32; d <<= 1) {
            unsigned int u = __shfl_up_sync(0xFFFFFFFFu, s, d);
            if (t >= d) s += u;
        }
        wsum[t] = s;
    }
    __syncthreads();
    if (t >= 32) v += wsum[(t >> 5) - 1];
    return v;
}

__global__ void scan1_kernel() {
    __shared__ unsigned int wsum[32];
    int i = blockIdx.x * 1024 + threadIdx.x;
    unsigned int sb = g_is64 ? SENTB64 : SENTB32;
    unsigned int c = g_bcnt[i] + ((unsigned int)i == sb ? g_sent : 0u);
    unsigned int v = blk_incl_scan_1024(c, wsum);
    g_incl[i] = v;
    if (threadIdx.x == 1023) g_bsum[blockIdx.x] = v;
}
__global__ void scan2_kernel() {
    __shared__ unsigned int wsum[32];
    unsigned int orig = g_bsum[threadIdx.x];
    unsigned int v = blk_incl_scan_1024(orig, wsum);
    g_bsum[threadIdx.x] = v - orig;   // exclusive
}
__global__ void scan3_kernel() {
    int i = blockIdx.x * blockDim.x + threadIdx.x;
    if (i >= NB) return;
    g_incl[i] += g_bsum[i >> 10];
}

// ---------------------------------------------------------------------------
// emit
// ---------------------------------------------------------------------------
__device__ void emit_run_bitonic(float* __restrict__ out, int E,
                                 unsigned int bucket, const unsigned short* row,
                                 long long base, unsigned int n,
                                 int sh, int is64, int lane) {
    unsigned int v = (lane < (int)n) ? (unsigned int)row[lane] : 0xFFFFFFFFu;
    #pragma unroll
    for (unsigned int k = 2; k <= 32; k <<= 1) {
        for (unsigned int j = k >> 1; j > 0; j >>= 1) {
            unsigned int o = __shfl_xor_sync(0xFFFFFFFFu, v, j);
            bool dirUp = ((lane & k) == 0);
            bool lower = ((lane & j) == 0);
            unsigned int mn = v < o ? v : o, mx = v < o ? o : v;
            v = (lower == dirUp) ? mn : mx;
        }
    }
    unsigned int prev = __shfl_up_sync(0xFFFFFFFFu, v, 1);
    if (lane < (int)n) {
        bool first = (lane == 0) || (v != prev);
        emit_pos(out, E, bucket, sh, is64, v, first, base + lane);
    }
}

// rare path: merge slab row + overflow list into smem buf, odd-even, emit
__device__ void emit_run_merged(float* __restrict__ out, int E,
                                unsigned int bucket, long long base,
                                unsigned int n, int sh, int is64, int lane,
                                unsigned short* buf, unsigned int* pcnt) {
    const unsigned short* row = g_slab + (size_t)bucket * CAP;
    for (unsigned int i = lane; i < CAP; i += 32) buf[i] = row[i];
    __syncwarp();
    if (lane == 0) {
        unsigned int cnt = CAP;
        unsigned int oc = g_ocnt; if (oc > OCAP) oc = OCAP;
        unsigned int mask = (1u << sh) - 1u;
        for (unsigned int i = 0; i < oc && cnt < MBUF; i++) {
            unsigned long long k = g_oflow[i];
            if ((unsigned int)(k >> sh) == bucket)
                buf[cnt++] = (unsigned short)((unsigned int)k & mask);
        }
        *pcnt = cnt;
    }
    __syncwarp();
    unsigned int cnt = *pcnt;
    if (n > cnt) n = cnt;             // (unreachable unless OCAP exceeded)
    for (unsigned int pass = 0; pass < n; ++pass) {
        unsigned int st = pass & 1u;
        for (unsigned int i = st + 2u * lane; i + 1 < n; i += 64u) {
            unsigned short x0 = buf[i], x1 = buf[i + 1];
            if (x0 > x1) { buf[i] = x1; buf[i + 1] = x0; }
        }
        __syncwarp();
    }
    for (unsigned int i = lane; i < n; i += 32) {
        unsigned int v = buf[i];
        bool first = (i == 0) || (v != (unsigned int)buf[i - 1]);
        emit_pos(out, E, bucket, sh, is64, v, first, base + i);
    }
}

__device__ void emit_bucket(float* __restrict__ out, int E, unsigned int bucket,
                            unsigned int startpos, unsigned int n,
                            int sh, int is64, int lane, unsigned int sentb,
                            unsigned short* buf, unsigned int* pcnt) {
    long long base = (long long)startpos;
    unsigned int nn = n;
    if (bucket == sentb) {
        unsigned int S = g_sent;
        if (S > n) S = n;
        const long long off_ei = OFF_EI;
        const long long off_em = off_ei + 2ll * E;
        for (unsigned int i = lane; i < S; i += 32) {
            long long p = base + i;
            out[off_ei + p]     = -1.0f;
            out[off_ei + E + p] = -1.0f;
            out[off_em + p]     = 0.0f;
        }
        base += S; nn = n - S;
        if (nn == 0) return;
    }
    if (nn <= 32) {
        emit_run_bitonic(out, E, bucket, g_slab + (size_t)bucket * CAP,
                         base, nn, sh, is64, lane);
    } else {
        emit_run_merged(out, E, bucket, base, nn, sh, is64, lane, buf, pcnt);
    }
}

// TWO buckets per warp: 16-lane sub-warp bitonic for n<=16 (common case)
__global__ void bucket_emit_kernel(float* __restrict__ out, int E) {
    __shared__ unsigned short mbuf[8][MBUF];
    __shared__ unsigned int  mcnt[8];
    int wib  = (int)(threadIdx.x >> 5);
    int gw   = (blockIdx.x * blockDim.x + threadIdx.x) >> 5;
    int lane = threadIdx.x & 31;
    unsigned int b0 = (unsigned int)gw * 2u;
    if (b0 >= NB) return;
    unsigned int start0 = (b0 == 0u) ? 0u : g_incl[b0 - 1];
    unsigned int end0   = g_incl[b0];
    unsigned int end1   = g_incl[b0 + 1];
    unsigned int n0 = end0 - start0, n1 = end1 - end0;
    if ((n0 | n1) == 0u) return;
    int is64 = g_is64;
    int sh = is64 ? 13 : 12;
    unsigned int sentb = is64 ? SENTB64 : SENTB32;

    if (n0 <= 16u && n1 <= 16u && b0 != sentb && b0 + 1 != sentb) {
        int half = lane >> 4, l = lane & 15;
        unsigned int start  = half ? end0 : start0;
        unsigned int n      = half ? n1 : n0;
        unsigned int bucket = b0 + (unsigned int)half;
        const unsigned short* row = g_slab + (size_t)bucket * CAP;
        unsigned int v = ((unsigned int)l < n) ? (unsigned int)row[l] : 0xFFFFFFFFu;
        #pragma unroll
        for (unsigned int k = 2; k <= 16; k <<= 1) {
            for (unsigned int j = k >> 1; j > 0; j >>= 1) {
                unsigned int o = __shfl_xor_sync(0xFFFFFFFFu, v, j);
                bool dirUp = (((unsigned int)l & k) == 0);
                bool lower = (((unsigned int)l & j) == 0);
                unsigned int mn = v < o ? v : o, mx = v < o ? o : v;
                v = (lower == dirUp) ? mn : mx;
            }
        }
        unsigned int prev = __shfl_up_sync(0xFFFFFFFFu, v, 1);
        if ((unsigned int)l < n) {
            bool first = (l == 0) || (v != prev);
            emit_pos(out, E, bucket, sh, is64, v, first,
                     (long long)(start + (unsigned int)l));
        }
    } else {
        if (n0) emit_bucket(out, E, b0,     start0, n0, sh, is64, lane, sentb,
                            mbuf[wib], &mcnt[wib]);
        if (n1) emit_bucket(out, E, b0 + 1, end0,   n1, sh, is64, lane, sentb,
                            mbuf[wib], &mcnt[wib]);
    }
}

__global__ void finalize_kernel(float* __restrict__ out) {
    int i = blockIdx.x * blockDim.x + threadIdx.x;
    if (i >= KC * DIM) return;
    {
        int c = i >> 6;
        float v = (g_counts[c] > 0u) ? dec_f32(g_xmax[i]) : 0.0f;
        out[i] = v;
    }
    if (i < KC * 3) {
        int c = i / 3;
        unsigned int cnt = g_counts[c];
        out[OFF_POS + i] = g_possum[i] / (float)(cnt > 0u ? cnt : 1u);
    }
    if (i < KC) {
        out[OFF_BATCH + i] = (float)(i / (NV0 * NV1));
        out[OFF_MASK + i]  = (g_counts[i] > 0u) ? 1.0f : 0.0f;
    }
}

// ---------------------------------------------------------------------------
// Launch: fork-join; fused edge pass is the 4th launch (profiled)
// ---------------------------------------------------------------------------
extern "C" void kernel_launch(void* const* d_in, const int* in_sizes, int n_in,
                              void* d_out, int out_size) {
    int ib = 0;
    for (int i = 1; i < n_in && i < 4; i++)
        if (in_sizes[i] < in_sizes[ib]) ib = i;
    long long N = in_sizes[ib];
    int ix = -1, ip = -1, ie = -1;
    for (int i = 0; i < n_in && i < 4; i++) {
        if (i == ib) continue;
        long long s = in_sizes[i];
        if (s == 64 * N)     ix = i;
        else if (s == 3 * N) ip = i;
        else                 ie = i;
    }
    if (ix < 0 || ip < 0 || ie < 0) { ix = 0; ip = 1; ib = 2; ie = 3; }

    const float* x    = (const float*)d_in[ix];
    const float* pos  = (const float*)d_in[ip];
    const void*  bat  = d_in[ib];
    const void*  eidx = d_in[ie];
    float*       out  = (float*)d_out;

    int Ni = (int)N;
    int E  = in_sizes[ie] / 2;
    if (Ni > N_MAX) Ni = N_MAX;
    if (E > E_MAX)  E  = E_MAX;

    static cudaStream_t s1 = nullptr;
    static cudaEvent_t evFork = nullptr, evJoin = nullptr;
    if (!s1) {
        cudaStreamCreateWithFlags(&s1, cudaStreamNonBlocking);
        cudaEventCreateWithFlags(&evFork, cudaEventDisableTiming);
        cudaEventCreateWithFlags(&evJoin, cudaEventDisableTiming);
    }

    const int T = 256;
    init_kernel<<<(KC * DIM / 4 + T - 1) / T, T>>>((const unsigned int*)eidx);  // 1
    cluster_kernel<<<(Ni + T - 1) / T, T>>>(pos, bat, Ni);                       // 2

    // fork: side stream runs xmax now, finalize later
    cudaEventRecord(evFork, 0);
    cudaStreamWaitEvent(s1, evFork, 0);
    xmax_kernel<<<(int)(((size_t)Ni * 32 + T - 1) / T), T, 0, s1>>>(x, Ni);     // 3

    edge_fused_kernel<<<(E + T - 1) / T, T>>>(eidx, Ni, E);                      // 4 <- profiled
    scan1_kernel<<<NBLK, 1024>>>();                                              // 5
    scan2_kernel<<<1, 1024>>>();                                                 // 6
    scan3_kernel<<<NB / 1024, 1024>>>();                                         // 7
    bucket_emit_kernel<<<NB / 16, T>>>(out, E);                                  // 8

    finalize_kernel<<<(KC * DIM + T - 1) / T, T, 0, s1>>>(out);                  // 9
    cudaEventRecord(evJoin, s1);
    cudaStreamWaitEvent(0, evJoin, 0);
    (void)out_size;
}

// round 16
// speedup vs baseline: 1.0971x; 1.0065x over previous
#include <cuda_runtime.h>
#include <stdint.h>

// ---------------------------------------------------------------------------
// Problem constants (DSEC 480x640, 4x4 voxels, B=4)
// ---------------------------------------------------------------------------
#define NV0 120
#define NV1 160
#define NBATCH 4
#define KC (NBATCH * NV0 * NV1)   /* 76800 */
#define DIM 64

#define N_MAX (1 << 20)
#define E_MAX (1 << 23)
#define NB (1 << 20)              /* sort buckets */
#define NBLK (NB / 1024)
#define CAP 32                    /* slab capacity per bucket (64MB, L2-resident) */
#define OCAP 8192                 /* overflow list capacity */
#define MBUF 128                  /* per-warp merge buffer */

// int32-wrapped sentinel: (int32)(76800*76800) = 1603272704
#define SENT32 1603272704
#define SENT64 5898240000ull
#define USENT32 3750756352u
#define SENTB32 (USENT32 >> 12)
#define SENTB64 ((unsigned)(SENT64 >> 13))

// Output layout (float32 flatten, reference return order):
#define OFF_POS   (KC * DIM)
#define OFF_BATCH (OFF_POS + KC * 3)
#define OFF_MASK  (OFF_BATCH + KC)
#define OFF_EI    (OFF_MASK + KC)

// ---------------------------------------------------------------------------
// Static device scratch
// ---------------------------------------------------------------------------
__device__ int            g_is64;
__device__ unsigned int   g_sent;
__device__ unsigned int   g_ocnt;
__device__ int            g_cluster[N_MAX];
__device__ unsigned int   g_counts[KC];
__device__ float          g_possum[KC * 3];
__device__ unsigned int   g_nodelist[N_MAX];  // node ids grouped by cluster
__device__ unsigned int   g_koff[KC];         // exclusive starts
__device__ unsigned int   g_kcur[KC];         // running cursors
__device__ unsigned short g_slab[(size_t)NB * CAP];
__device__ unsigned long long g_oflow[OCAP];
__device__ unsigned int   g_bcnt[NB];
__device__ unsigned int   g_incl[NB];
__device__ unsigned int   g_bsum[NBLK];

__device__ __forceinline__ int ld_id(const void* p, long long i, int is64) {
    return is64 ? (int)((const long long*)p)[i] : ((const int*)p)[i];
}
__device__ __forceinline__ int clampi(int v, int lo, int hi) {
    return v < lo ? lo : (v > hi ? hi : v);
}

__device__ __forceinline__ unsigned int edge_k32(int sc, int dc) {
    int key32 = (sc == dc) ? SENT32
              : (int)((unsigned int)sc * 76800u + (unsigned int)dc);
    return ((unsigned int)key32) ^ 0x80000000u;
}
__device__ __forceinline__ unsigned long long edge_uk64(int sc, int dc) {
    if (sc == dc) return SENT64;
    return (unsigned long long)(unsigned int)sc * 76800ull
         + (unsigned long long)(unsigned int)dc;
}

// i32 decode via magic division. 76800 = 2^10*75; floor-div fixup 2^31 = 76800*27962+2048
__device__ __forceinline__ void decode32(unsigned int uk,
                                         float* sf, float* df, bool* valid) {
    *valid = (uk < USENT32);
    unsigned int q = __umulhi(uk >> 10, 57266231u);
    unsigned int r = uk - q * 76800u;
    int qf; unsigned int rf;
    if (r >= 2048u) { qf = (int)q - 27962; rf = r - 2048u; }
    else            { qf = (int)q - 27963; rf = r + 74752u; }
    *sf = (float)qf;
    *df = (float)rf;
}
__device__ __forceinline__ void decode_key(unsigned long long uk, int is64,
                                           float* sf, float* df, bool* valid) {
    if (is64) {
        *valid = (uk < SENT64);
        *sf = (float)(long long)(uk / 76800ull);
        *df = (float)(long long)(uk % 76800ull);
    } else {
        decode32((unsigned int)uk, sf, df, valid);
    }
}

__device__ __forceinline__ void emit_pos(float* __restrict__ out, int E,
                                         unsigned int bucket,
                                         int sh, int is64, unsigned int v,
                                         bool first, long long p) {
    const long long off_ei = OFF_EI;
    const long long off_em = off_ei + 2ll * E;
    unsigned long long uk = (((unsigned long long)bucket) << sh) | v;
    float sf, df; bool valid;
    decode_key(uk, is64, &sf, &df, &valid);
    bool mask = first && valid;
    out[off_ei + p]     = mask ? sf   : -1.0f;
    out[off_ei + E + p] = mask ? df   : -1.0f;
    out[off_em + p]     = mask ? 1.0f : 0.0f;
}

// ---------------------------------------------------------------------------
// init (+ dtype sniff)
// ---------------------------------------------------------------------------
__global__ void init_kernel(const unsigned int* ew) {
    int i = blockIdx.x * blockDim.x + threadIdx.x;
    if (i == 0) {
        unsigned int o = 0;
        for (int k = 1; k < 128; k += 2) o |= ew[k];
        g_is64 = (o == 0u) ? 1 : 0;
        g_sent = 0u;
        g_ocnt = 0u;
    }
    if (i >= NB / 4) return;
    ((uint4*)g_bcnt)[i] = make_uint4(0u, 0u, 0u, 0u);
    if (i < KC / 4)     ((uint4*)g_counts)[i] = make_uint4(0u, 0u, 0u, 0u);
    if (i < KC * 3 / 4) ((uint4*)g_possum)[i] = make_uint4(0u, 0u, 0u, 0u);
}

// ---------------------------------------------------------------------------
// cluster: one thread per node
// ---------------------------------------------------------------------------
__global__ void cluster_kernel(const float* __restrict__ pos,
                               const void* batch, int N) {
    int i = blockIdx.x * blockDim.x + threadIdx.x;
    if (i >= N) return;
    int is64 = g_is64;
    float p0 = pos[3 * i + 0];
    float p1 = pos[3 * i + 1];
    float p2 = pos[3 * i + 2];
    int c0 = clampi((int)floorf(p1 * 0.25f), 0, NV0 - 1);
    int c1 = clampi((int)floorf(p2 * 0.25f), 0, NV1 - 1);
    int b  = clampi(ld_id(batch, i, is64), 0, NBATCH - 1);
    int c  = c0 + c1 * NV0 + b * (NV0 * NV1);
    g_cluster[i] = c;
    atomicAdd(&g_counts[c], 1u);
    atomicAdd(&g_possum[3 * c + 0], p0);
    atomicAdd(&g_possum[3 * c + 1], p1);
    atomicAdd(&g_possum[3 * c + 2], p2);
}

// node-chain: exclusive scan of cluster counts (76800 = 1024*75, one block)
__global__ void nodescan_kernel() {
    __shared__ unsigned int sums[1024];
    const int PER = KC / 1024;  // 75
    int t = threadIdx.x;
    unsigned int s = 0;
    #pragma unroll 5
    for (int i = 0; i < PER; i++) s += g_counts[t * PER + i];
    sums[t] = s;
    __syncthreads();
    for (int d = 1; d < 1024; d <<= 1) {
        unsigned int v = (t >= d) ? sums[t - d] : 0u;
        __syncthreads();
        sums[t] += v;
        __syncthreads();
    }
    unsigned int prefix = (t == 0) ? 0u : sums[t - 1];
    for (int i = 0; i < PER; i++) {
        g_koff[t * PER + i] = prefix;
        g_kcur[t * PER + i] = prefix;
        prefix += g_counts[t * PER + i];
    }
}

// bucket node ids by cluster: 1 atomic + 1 store per node
__global__ void nodescatter_kernel(int N) {
    int i = blockIdx.x * blockDim.x + threadIdx.x;
    if (i >= N) return;
    int c = g_cluster[i];
    unsigned int pos = atomicAdd(&g_kcur[c], 1u);
    if (pos < (unsigned int)N) g_nodelist[pos] = (unsigned int)i;
}

// gather-max: one warp per cluster, running max in registers, write x_out
__global__ void xmax2_kernel(const float* __restrict__ x,
                             float* __restrict__ out, int N) {
    int c    = (blockIdx.x * blockDim.x + threadIdx.x) >> 5;
    int lane = threadIdx.x & 31;
    if (c >= KC) return;
    unsigned int n     = g_counts[c];
    unsigned int start = g_koff[c];
    float2 acc = make_float2(-__int_as_float(0x7F800000), -__int_as_float(0x7F800000));
    for (unsigned int m = 0; m < n; m++) {
        unsigned int nid = g_nodelist[start + m];
        float2 v = ((const float2*)(x + (size_t)nid * DIM))[lane];
        acc.x = fmaxf(acc.x, v.x);
        acc.y = fmaxf(acc.y, v.y);
    }
    if (n == 0) acc = make_float2(0.0f, 0.0f);
    ((float2*)out)[(size_t)c * 32 + lane] = acc;
}

// pos/batch/mask outputs (x_out handled by xmax2)
__global__ void finalize_kernel(float* __restrict__ out) {
    int i = blockIdx.x * blockDim.x + threadIdx.x;
    if (i >= KC * 3) return;
    {
        int c = i / 3;
        unsigned int cnt = g_counts[c];
        out[OFF_POS + i] = g_possum[i] / (float)(cnt > 0u ? cnt : 1u);
    }
    if (i < KC) {
        out[OFF_BATCH + i] = (float)(i / (NV0 * NV1));
        out[OFF_MASK + i]  = (g_counts[i] > 0u) ? 1.0f : 0.0f;
    }
}

// ---------------------------------------------------------------------------
// FUSED edge pass: gather clusters -> key -> count+store into bucket slab.
// ---------------------------------------------------------------------------
__device__ __forceinline__ void place32(unsigned int k) {
    if (k == USENT32) {
        atomicAdd(&g_sent, 1u);
    } else {
        unsigned int b = k >> 12;
        unsigned int pos = atomicAdd(&g_bcnt[b], 1u);
        if (pos < CAP) {
            g_slab[(size_t)b * CAP + pos] = (unsigned short)(k & 0xFFFu);
        } else {
            unsigned int o = atomicAdd(&g_ocnt, 1u);
            if (o < OCAP) g_oflow[o] = (unsigned long long)k;
        }
    }
}

__global__ void edge_fused_kernel(const void* eidx, int N, int E) {
    int t = blockIdx.x * blockDim.x + threadIdx.x;
    int is64 = g_is64;
    if (!is64) {
        if ((E & 3) == 0) {
            int nq = E >> 2;
            if (t >= nq) return;
            int4 uu = ((const int4*)eidx)[t];
            int4 vv = ((const int4*)((const int*)eidx + E))[t];
            int sc0 = g_cluster[clampi(uu.x, 0, N - 1)];
            int sc1 = g_cluster[clampi(uu.y, 0, N - 1)];
            int sc2 = g_cluster[clampi(uu.z, 0, N - 1)];
            int sc3 = g_cluster[clampi(uu.w, 0, N - 1)];
            int dc0 = g_cluster[clampi(vv.x, 0, N - 1)];
            int dc1 = g_cluster[clampi(vv.y, 0, N - 1)];
            int dc2 = g_cluster[clampi(vv.z, 0, N - 1)];
            int dc3 = g_cluster[clampi(vv.w, 0, N - 1)];
            place32(edge_k32(sc0, dc0));
            place32(edge_k32(sc1, dc1));
            place32(edge_k32(sc2, dc2));
            place32(edge_k32(sc3, dc3));
        } else {
            if (t >= E) return;
            int u = clampi(((const int*)eidx)[t], 0, N - 1);
            int v = clampi(((const int*)eidx)[(size_t)E + t], 0, N - 1);
            place32(edge_k32(g_cluster[u], g_cluster[v]));
        }
    } else {
        if (t >= E) return;
        int u = clampi(ld_id(eidx, t, 1), 0, N - 1);
        int v = clampi(ld_id(eidx, (long long)E + t, 1), 0, N - 1);
        unsigned long long uk = edge_uk64(g_cluster[u], g_cluster[v]);
        if (uk == SENT64) {
            atomicAdd(&g_sent, 1u);
        } else {
            unsigned int b = (unsigned int)(uk >> 13);
            unsigned int pos = atomicAdd(&g_bcnt[b], 1u);
            if (pos < CAP) {
                g_slab[(size_t)b * CAP + pos] = (unsigned short)(uk & 0x1FFFu);
            } else {
                unsigned int o = atomicAdd(&g_ocnt, 1u);
                if (o < OCAP) g_oflow[o] = uk;
            }
        }
    }
}

// -- shfl-based scans --------------------------------------------------------
__device__ __forceinline__ unsigned int blk_incl_scan_1024(unsigned int v,
                                                           unsigned int* wsum) {
    int t = threadIdx.x;
    #pragma unroll
    for (int d = 1; d < 32; d <<= 1) {
        unsigned int u = __shfl_up_sync(0xFFFFFFFFu, v, d);
        if ((t & 31) >= d) v += u;
    }
    if ((t & 31) == 31) wsum[t >> 5] = v;
    __syncthreads();
    if (t < 32) {
        unsigned int s = wsum[t];
        #pragma unroll
        for (int d = 1; d < 32; d <<= 1) {
            unsigned int u = __shfl_up_sync(0xFFFFFFFFu, s, d);
            if (t >= d) s += u;
        }
        wsum[t] = s;
    }
    __syncthreads();
    if (t >= 32) v += wsum[(t >> 5) - 1];
    return v;
}

__global__ void scan1_kernel() {
    __shared__ unsigned int wsum[32];
    int i = blockIdx.x * 1024 + threadIdx.x;
    unsigned int sb = g_is64 ? SENTB64 : SENTB32;
    unsigned int c = g_bcnt[i] + ((unsigned int)i == sb ? g_sent : 0u);
    unsigned int v = blk_incl_scan_1024(c, wsum);
    g_incl[i] = v;
    if (threadIdx.x == 1023) g_bsum[blockIdx.x] = v;
}
__global__ void scan2_kernel() {
    __shared__ unsigned int wsum[32];
    unsigned int orig = g_bsum[threadIdx.x];
    unsigned int v = blk_incl_scan_1024(orig, wsum);
    g_bsum[threadIdx.x] = v - orig;
}
__global__ void scan3_kernel() {
    int i = blockIdx.x * blockDim.x + threadIdx.x;
    if (i >= NB) return;
    g_incl[i] += g_bsum[i >> 10];
}

// ---------------------------------------------------------------------------
// emit
// ---------------------------------------------------------------------------
__device__ void emit_run_bitonic(float* __restrict__ out, int E,
                                 unsigned int bucket, const unsigned short* row,
                                 long long base, unsigned int n,
                                 int sh, int is64, int lane) {
    unsigned int v = (lane < (int)n) ? (unsigned int)row[lane] : 0xFFFFFFFFu;
    #pragma unroll
    for (unsigned int k = 2; k <= 32; k <<= 1) {
        for (unsigned int j = k >> 1; j > 0; j >>= 1) {
            unsigned int o = __shfl_xor_sync(0xFFFFFFFFu, v, j);
            bool dirUp = ((lane & k) == 0);
            bool lower = ((lane & j) == 0);
            unsigned int mn = v < o ? v : o, mx = v < o ? o : v;
            v = (lower == dirUp) ? mn : mx;
        }
    }
    unsigned int prev = __shfl_up_sync(0xFFFFFFFFu, v, 1);
    if (lane < (int)n) {
        bool first = (lane == 0) || (v != prev);
        emit_pos(out, E, bucket, sh, is64, v, first, base + lane);
    }
}

__device__ void emit_run_merged(float* __restrict__ out, int E,
                                unsigned int bucket, long long base,
                                unsigned int n, int sh, int is64, int lane,
                                unsigned short* buf, unsigned int* pcnt) {
    const unsigned short* row = g_slab + (size_t)bucket * CAP;
    for (unsigned int i = lane; i < CAP; i += 32) buf[i] = row[i];
    __syncwarp();
    if (lane == 0) {
        unsigned int cnt = CAP;
        unsigned int oc = g_ocnt; if (oc > OCAP) oc = OCAP;
        unsigned int mask = (1u << sh) - 1u;
        for (unsigned int i = 0; i < oc && cnt < MBUF; i++) {
            unsigned long long k = g_oflow[i];
            if ((unsigned int)(k >> sh) == bucket)
                buf[cnt++] = (unsigned short)((unsigned int)k & mask);
        }
        *pcnt = cnt;
    }
    __syncwarp();
    unsigned int cnt = *pcnt;
    if (n > cnt) n = cnt;
    for (unsigned int pass = 0; pass < n; ++pass) {
        unsigned int st = pass & 1u;
        for (unsigned int i = st + 2u * lane; i + 1 < n; i += 64u) {
            unsigned short x0 = buf[i], x1 = buf[i + 1];
            if (x0 > x1) { buf[i] = x1; buf[i + 1] = x0; }
        }
        __syncwarp();
    }
    for (unsigned int i = lane; i < n; i += 32) {
        unsigned int v = buf[i];
        bool first = (i == 0) || (v != (unsigned int)buf[i - 1]);
        emit_pos(out, E, bucket, sh, is64, v, first, base + i);
    }
}

__device__ void emit_bucket(float* __restrict__ out, int E, unsigned int bucket,
                            unsigned int startpos, unsigned int n,
                            int sh, int is64, int lane, unsigned int sentb,
                            unsigned short* buf, unsigned int* pcnt) {
    long long base = (long long)startpos;
    unsigned int nn = n;
    if (bucket == sentb) {
        unsigned int S = g_sent;
        if (S > n) S = n;
        const long long off_ei = OFF_EI;
        const long long off_em = off_ei + 2ll * E;
        for (unsigned int i = lane; i < S; i += 32) {
            long long p = base + i;
            out[off_ei + p]     = -1.0f;
            out[off_ei + E + p] = -1.0f;
            out[off_em + p]     = 0.0f;
        }
        base += S; nn = n - S;
        if (nn == 0) return;
    }
    if (nn <= 32) {
        emit_run_bitonic(out, E, bucket, g_slab + (size_t)bucket * CAP,
                         base, nn, sh, is64, lane);
    } else {
        emit_run_merged(out, E, bucket, base, nn, sh, is64, lane, buf, pcnt);
    }
}

__global__ void bucket_emit_kernel(float* __restrict__ out, int E) {
    __shared__ unsigned short mbuf[8][MBUF];
    __shared__ unsigned int  mcnt[8];
    int wib  = (int)(threadIdx.x >> 5);
    int gw   = (blockIdx.x * blockDim.x + threadIdx.x) >> 5;
    int lane = threadIdx.x & 31;
    unsigned int b0 = (unsigned int)gw * 2u;
    if (b0 >= NB) return;
    unsigned int start0 = (b0 == 0u) ? 0u : g_incl[b0 - 1];
    unsigned int end0   = g_incl[b0];
    unsigned int end1   = g_incl[b0 + 1];
    unsigned int n0 = end0 - start0, n1 = end1 - end0;
    if ((n0 | n1) == 0u) return;
    int is64 = g_is64;
    int sh = is64 ? 13 : 12;
    unsigned int sentb = is64 ? SENTB64 : SENTB32;

    if (n0 <= 16u && n1 <= 16u && b0 != sentb && b0 + 1 != sentb) {
        int half = lane >> 4, l = lane & 15;
        unsigned int start  = half ? end0 : start0;
        unsigned int n      = half ? n1 : n0;
        unsigned int bucket = b0 + (unsigned int)half;
        const unsigned short* row = g_slab + (size_t)bucket * CAP;
        unsigned int v = ((unsigned int)l < n) ? (unsigned int)row[l] : 0xFFFFFFFFu;
        #pragma unroll
        for (unsigned int k = 2; k <= 16; k <<= 1) {
            for (unsigned int j = k >> 1; j > 0; j >>= 1) {
                unsigned int o = __shfl_xor_sync(0xFFFFFFFFu, v, j);
                bool dirUp = (((unsigned int)l & k) == 0);
                bool lower = (((unsigned int)l & j) == 0);
                unsigned int mn = v < o ? v : o, mx = v < o ? o : v;
                v = (lower == dirUp) ? mn : mx;
            }
        }
        unsigned int prev = __shfl_up_sync(0xFFFFFFFFu, v, 1);
        if ((unsigned int)l < n) {
            bool first = (l == 0) || (v != prev);
            emit_pos(out, E, bucket, sh, is64, v, first,
                     (long long)(start + (unsigned int)l));
        }
    } else {
        if (n0) emit_bucket(out, E, b0,     start0, n0, sh, is64, lane, sentb,
                            mbuf[wib], &mcnt[wib]);
        if (n1) emit_bucket(out, E, b0 + 1, end0,   n1, sh, is64, lane, sentb,
                            mbuf[wib], &mcnt[wib]);
    }
}

// ---------------------------------------------------------------------------
// Launch: fork-join — edge chain (main) || node chain (side)
// ---------------------------------------------------------------------------
extern "C" void kernel_launch(void* const* d_in, const int* in_sizes, int n_in,
                              void* d_out, int out_size) {
    int ib = 0;
    for (int i = 1; i < n_in && i < 4; i++)
        if (in_sizes[i] < in_sizes[ib]) ib = i;
    long long N = in_sizes[ib];
    int ix = -1, ip = -1, ie = -1;
    for (int i = 0; i < n_in && i < 4; i++) {
        if (i == ib) continue;
        long long s = in_sizes[i];
        if (s == 64 * N)     ix = i;
        else if (s == 3 * N) ip = i;
        else                 ie = i;
    }
    if (ix < 0 || ip < 0 || ie < 0) { ix = 0; ip = 1; ib = 2; ie = 3; }

    const float* x    = (const float*)d_in[ix];
    const float* pos  = (const float*)d_in[ip];
    const void*  bat  = d_in[ib];
    const void*  eidx = d_in[ie];
    float*       out  = (float*)d_out;

    int Ni = (int)N;
    int E  = in_sizes[ie] / 2;
    if (Ni > N_MAX) Ni = N_MAX;
    if (E > E_MAX)  E  = E_MAX;

    static cudaStream_t s1 = nullptr;
    static cudaEvent_t evFork = nullptr, evJoin = nullptr;
    if (!s1) {
        cudaStreamCreateWithFlags(&s1, cudaStreamNonBlocking);
        cudaEventCreateWithFlags(&evFork, cudaEventDisableTiming);
        cudaEventCreateWithFlags(&evJoin, cudaEventDisableTiming);
    }

    const int T = 256;
    init_kernel<<<(NB / 4 + T - 1) / T, T>>>((const unsigned int*)eidx);        // 1
    cluster_kernel<<<(Ni + T - 1) / T, T>>>(pos, bat, Ni);                       // 2

    // fork: side stream runs the node chain (few LTS ops, DRAM-streaming)
    cudaEventRecord(evFork, 0);
    cudaStreamWaitEvent(s1, evFork, 0);
    nodescan_kernel<<<1, 1024, 0, s1>>>();                                       // 3

    edge_fused_kernel<<<(E + T - 1) / T, T>>>(eidx, Ni, E);                      // 4 <- profiled

    nodescatter_kernel<<<(Ni + T - 1) / T, T, 0, s1>>>(Ni);                      // 5
    xmax2_kernel<<<(KC * 32 + T - 1) / T, T, 0, s1>>>(x, out, Ni);               // 6
    finalize_kernel<<<(KC * 3 + T - 1) / T, T, 0, s1>>>(out);                    // 7
    cudaEventRecord(evJoin, s1);

    scan1_kernel<<<NBLK, 1024>>>();                                              // 8
    scan2_kernel<<<1, 1024>>>();                                                 // 9
    scan3_kernel<<<NB / 1024, 1024>>>();                                         // 10
    bucket_emit_kernel<<<NB / 16, T>>>(out, E);                                  // 11

    cudaStreamWaitEvent(0, evJoin, 0);
    (void)out_size;
}